// round 7
// baseline (speedup 1.0000x reference)
#include <cuda_runtime.h>
#include <cuda_bf16.h>
#include <math.h>

// Problem constants
#define B_    2
#define L_    2048
#define D_    2048
#define H_    16
#define KVH_  4
#define DK_   128
#define DKV_  512            // KVH_ * DK_
#define M_    (B_ * L_)      // 4096 rows
#define CAPV  50.0f

// ---------------- scratch (static device globals; no allocation) ----------------
static __device__ float g_Q[(size_t)M_ * D_];
static __device__ float g_K[(size_t)M_ * DKV_];
static __device__ float g_V[(size_t)M_ * DKV_];
static __device__ float g_O[(size_t)M_ * D_];
static __device__ float g_cos[L_ * 64];
static __device__ float g_sin[L_ * 64];

// ---------------- RoPE table ----------------
__global__ void rope_table_kernel() {
    int idx = blockIdx.x * blockDim.x + threadIdx.x;
    if (idx >= L_ * 64) return;
    int pos = idx >> 6;
    int i   = idx & 63;
    float expnt = (float)(2 * i) / 128.0f;
    float invf  = powf(10000.0f, -expnt);
    float f     = (float)pos * invf;
    g_cos[idx] = cosf(f);
    g_sin[idx] = sinf(f);
}

// ---------------- RoPE apply + clip (in place) ----------------
__global__ void rope_apply_kernel(float* __restrict__ X, int heads, int rowstride) {
    int idx   = blockIdx.x * blockDim.x + threadIdx.x;
    int total = M_ * heads * 64;
    if (idx >= total) return;
    int i   = idx & 63;
    int t   = idx >> 6;
    int h   = t % heads;
    int row = t / heads;
    int pos = row & (L_ - 1);
    float c = g_cos[(pos << 6) + i];
    float s = g_sin[(pos << 6) + i];
    float* p = X + (size_t)row * rowstride + h * DK_ + i;
    float x1 = p[0], x2 = p[64];
    float o1 = x1 * c - x2 * s;
    float o2 = x1 * s + x2 * c;
    p[0]  = fminf(fmaxf(o1, -CAPV), CAPV);
    p[64] = fminf(fmaxf(o2, -CAPV), CAPV);
}

// ---------------- tf32 / cp.async helpers ----------------
__device__ __forceinline__ float to_tf32(float x) {
    float r;
    asm("cvt.rna.tf32.f32 %0, %1;" : "=f"(r) : "f"(x));
    return r;
}

__device__ __forceinline__ float4 to_tf32_4(float4 v) {
    return make_float4(to_tf32(v.x), to_tf32(v.y), to_tf32(v.z), to_tf32(v.w));
}

__device__ __forceinline__ void mma_tf32(float* c, const float4& a, const float2& b) {
    const unsigned* A  = reinterpret_cast<const unsigned*>(&a);
    const unsigned* Bv = reinterpret_cast<const unsigned*>(&b);
    asm volatile(
        "mma.sync.aligned.m16n8k8.row.col.f32.tf32.tf32.f32 "
        "{%0,%1,%2,%3}, {%4,%5,%6,%7}, {%8,%9}, {%0,%1,%2,%3};"
        : "+f"(c[0]), "+f"(c[1]), "+f"(c[2]), "+f"(c[3])
        : "r"(A[0]), "r"(A[1]), "r"(A[2]), "r"(A[3]), "r"(Bv[0]), "r"(Bv[1]));
}

__device__ __forceinline__ void cp16(float* smem_dst, const float* gsrc) {
    unsigned saddr = (unsigned)__cvta_generic_to_shared(smem_dst);
    asm volatile("cp.async.ca.shared.global [%0], [%1], 16;" :: "r"(saddr), "l"(gsrc));
}
__device__ __forceinline__ void cp_commit() {
    asm volatile("cp.async.commit_group;");
}
template <int N>
__device__ __forceinline__ void cp_wait() {
    asm volatile("cp.async.wait_group %0;" :: "n"(N));
}

// ---------------- tf32 NT GEMM v3: cp.async 3-stage, 512 threads ----------------
// C[M,N] = A[M,K] * Bw[N,K]^T.  BM=BN=128, BK=32.
// 16 warps (4x4), warp tile 32x32, thread frags mt(2) x nt(4), 32 acc/thread.
// smem: raw fp32 tiles, pitch 36 (=4 mod 32 -> conflict-free frag gathers),
// tf32 cvt on fragment load. ONE __syncthreads per k-tile:
//   [wait g_kt; barrier; issue g_{kt+2} (into buffer freed by iter kt-1,
//    safe because every thread passed this barrier after computing kt-1); compute kt]
#define GSTAGES 3
#define GEMM_TILE_F   (128 * 36)
#define GEMM_SMEM_BYTES (GSTAGES * 2 * GEMM_TILE_F * 4)   // 110592 B

__global__ void __launch_bounds__(512, 1) gemm_tf32_kernel(
    const float* __restrict__ A, const float* __restrict__ Bw,
    float* __restrict__ C, int M, int N, int K)
{
    extern __shared__ float smg[];

    const int tid    = threadIdx.x;
    const int lane   = tid & 31;
    const int wid    = tid >> 5;
    const int warp_m = wid & 3;     // 32 rows each
    const int warp_n = wid >> 2;    // 32 cols each
    const int bm     = blockIdx.y << 7;
    const int bn     = blockIdx.x << 7;
    const int m_     = lane & 3;
    const int rr     = lane >> 2;

    float acc[2][4][4];
    #pragma unroll
    for (int mt = 0; mt < 2; mt++)
        #pragma unroll
        for (int nt = 0; nt < 4; nt++)
            #pragma unroll
            for (int r = 0; r < 4; r++) acc[mt][nt][r] = 0.0f;

    auto issue_stage = [&](int kt, int s) {
        float* dA = smg + s * 2 * GEMM_TILE_F;
        float* dB = dA + GEMM_TILE_F;
        const int koff = kt << 5;
        #pragma unroll
        for (int i = 0; i < 2; i++) {
            int idx = tid + (i << 9);      // 0..1023
            int row = idx >> 3;
            int c4  = idx & 7;
            cp16(dA + row * 36 + (c4 << 2), A  + (size_t)(bm + row) * K + koff + (c4 << 2));
            cp16(dB + row * 36 + (c4 << 2), Bw + (size_t)(bn + row) * K + koff + (c4 << 2));
        }
        cp_commit();
    };

    const int stages = K >> 5;
    issue_stage(0, 0);
    if (stages > 1) issue_stage(1, 1);

    int s = 0;
    for (int kt = 0; kt < stages; kt++) {
        if (kt == stages - 1) cp_wait<0>(); else cp_wait<1>();
        __syncthreads();
        if (kt + 2 < stages) {
            int s2 = s + 2; if (s2 >= GSTAGES) s2 -= GSTAGES;
            issue_stage(kt + 2, s2);
        }

        const float* rA = smg + s * 2 * GEMM_TILE_F + (warp_m * 32 + rr) * 36;
        const float* rB = rA + GEMM_TILE_F + (warp_n * 32 - warp_m * 32) * 36;
        #pragma unroll
        for (int ks = 0; ks < 4; ks++) {
            const int c = (ks << 3) + m_;
            float4 a[2];
            float2 b[4];
            #pragma unroll
            for (int mt = 0; mt < 2; mt++) {
                const float* p = rA + mt * 16 * 36 + c;
                a[mt] = make_float4(to_tf32(p[0]), to_tf32(p[8 * 36]),
                                    to_tf32(p[4]), to_tf32(p[8 * 36 + 4]));
            }
            #pragma unroll
            for (int nt = 0; nt < 4; nt++) {
                const float* p = rB + nt * 8 * 36 + c;
                b[nt] = make_float2(to_tf32(p[0]), to_tf32(p[4]));
            }
            #pragma unroll
            for (int mt = 0; mt < 2; mt++)
                #pragma unroll
                for (int nt = 0; nt < 4; nt++)
                    mma_tf32(acc[mt][nt], a[mt], b[nt]);
        }
        if (++s >= GSTAGES) s -= GSTAGES;
    }

    const int g   = lane >> 2;
    const int tig = lane & 3;
    #pragma unroll
    for (int mt = 0; mt < 2; mt++) {
        int r0 = bm + warp_m * 32 + mt * 16 + g;
        #pragma unroll
        for (int nt = 0; nt < 4; nt++) {
            int c = bn + warp_n * 32 + nt * 8 + (tig << 1);
            *(float2*)(&C[(size_t)r0 * N + c])       = make_float2(acc[mt][nt][0], acc[mt][nt][1]);
            *(float2*)(&C[(size_t)(r0 + 8) * N + c]) = make_float2(acc[mt][nt][2], acc[mt][nt][3]);
        }
    }
}

// ---------------- tf32 tensor-core flash attention (causal) ----------------
// Structure as R5 (row-major pitched smem, conflict-free gathers) plus software
// pipelining: K(kb+1) LDGs issued during V-store/PV window; V LDGs issued before
// softmax so softmax hides their latency.
//   Qs  float[64*132] @0, KVs float[64*136] @8448 (K pitch 132 / V pitch 136),
//   Ps  float[64*68] @17152, smM/L/F @21504.
#define ATTN_SMEM_BYTES 86784

__global__ void __launch_bounds__(256, 2) attn_kernel() {
    extern __shared__ float smf[];
    float* Qs  = smf;
    float* KVs = smf + 8448;
    float* Ps  = smf + 17152;
    float* smM = smf + 21504;
    float* smL = smM + 64;
    float* smF = smL + 64;

    const int tid  = threadIdx.x;
    const int lane = tid & 31;
    const int wid  = tid >> 5;
    const int wm   = wid & 3;
    const int wn   = wid >> 2;
    const int m_   = lane & 3;
    const int rr   = lane >> 2;

    const int qb  = blockIdx.x;
    const int h   = blockIdx.y;
    const int b   = blockIdx.z;
    const int q0  = qb << 6;
    const int kvh = h >> 2;

    const float* Qg = g_Q + (size_t)(b * L_ + q0) * D_ + h * DK_;
    const float* Kg = g_K + (size_t)(b * L_) * DKV_ + kvh * DK_;
    const float* Vg = g_V + (size_t)(b * L_) * DKV_ + kvh * DK_;

    // per-thread tile coords for 64x128 tile staging
    const int trow = tid >> 5;              // +8 per it
    const int tc4  = (tid & 31) << 2;

    // ---- load Q (tf32, pitch 132) ----
    #pragma unroll
    for (int it = 0; it < 8; it++) {
        int row = trow + (it << 3);
        float4 v = *(const float4*)(Qg + (size_t)row * D_ + tc4);
        *(float4*)&Qs[row * 132 + tc4] = to_tf32_4(v);
    }
    if (tid < 64) { smM[tid] = -1e30f; smL[tid] = 0.0f; }

    // ---- prefetch K(0) ----
    float4 kreg[8];
    #pragma unroll
    for (int it = 0; it < 8; it++) {
        int row = trow + (it << 3);
        kreg[it] = *(const float4*)(Kg + (size_t)row * DKV_ + tc4);
    }

    float o[8][4];
    #pragma unroll
    for (int j = 0; j < 8; j++)
        #pragma unroll
        for (int r = 0; r < 4; r++) o[j][r] = 0.0f;

    const float scale = 0.08838834764831845f;  // 1/sqrt(128)
    const int nkb = qb + 1;

    for (int kb = 0; kb < nkb; kb++) {
        const int k0 = kb << 6;
        __syncthreads();   // (A) prev PV done reading KVs/Ps

        // ---- store K(kb) from regs (tf32, pitch 132) ----
        #pragma unroll
        for (int it = 0; it < 8; it++) {
            int row = trow + (it << 3);
            *(float4*)&KVs[row * 132 + tc4] = to_tf32_4(kreg[it]);
        }
        __syncthreads();   // (B) K tile ready

        // ---- S = Q K^T via mma ----
        {
            float s4[4][4];
            #pragma unroll
            for (int j = 0; j < 4; j++)
                #pragma unroll
                for (int r = 0; r < 4; r++) s4[j][r] = 0.0f;

            const float* qbase = &Qs[(wm * 16 + rr) * 132];
            const float* kbase = &KVs[(wn * 32 + rr) * 132];
            #pragma unroll
            for (int ks = 0; ks < 16; ks++) {
                const int c = (ks << 3) + m_;
                const float* qp = qbase + c;
                float4 a = make_float4(qp[0], qp[8 * 132], qp[4], qp[8 * 132 + 4]);
                #pragma unroll
                for (int j = 0; j < 4; j++) {
                    const float* kp = kbase + j * 8 * 132 + c;
                    float2 bfr = make_float2(kp[0], kp[4]);
                    mma_tf32(s4[j], a, bfr);
                }
            }

            int r0 = wm * 16 + rr;
            int r1 = r0 + 8;
            #pragma unroll
            for (int j = 0; j < 4; j++) {
                int c0 = (wn * 4 + j) * 8 + (m_ << 1);
                float v00 = s4[j][0] * scale, v01 = s4[j][1] * scale;
                float v10 = s4[j][2] * scale, v11 = s4[j][3] * scale;
                if (k0 + c0     > q0 + r0) v00 = -1e30f;
                if (k0 + c0 + 1 > q0 + r0) v01 = -1e30f;
                if (k0 + c0     > q0 + r1) v10 = -1e30f;
                if (k0 + c0 + 1 > q0 + r1) v11 = -1e30f;
                *(float2*)&Ps[r0 * 68 + c0] = make_float2(v00, v01);
                *(float2*)&Ps[r1 * 68 + c0] = make_float2(v10, v11);
            }
        }
        __syncthreads();   // (C) Ps ready; K reads done -> KVs reusable for V

        // ---- issue V(kb) loads (latency hidden by softmax) ----
        float4 vreg[8];
        #pragma unroll
        for (int it = 0; it < 8; it++) {
            int row = trow + (it << 3);
            vreg[it] = *(const float4*)(Vg + (size_t)(k0 + row) * DKV_ + tc4);
        }

        // ---- online softmax: 4 threads per row; exp back to Ps (tf32) ----
        {
            int r   = tid >> 2;
            int seg = tid & 3;
            float v[16];
            #pragma unroll
            for (int q = 0; q < 4; q++) {
                float4 t = *(float4*)&Ps[r * 68 + seg * 16 + (q << 2)];
                v[q * 4 + 0] = t.x; v[q * 4 + 1] = t.y;
                v[q * 4 + 2] = t.z; v[q * 4 + 3] = t.w;
            }
            float mx = v[0];
            #pragma unroll
            for (int q = 1; q < 16; q++) mx = fmaxf(mx, v[q]);
            mx = fmaxf(mx, __shfl_xor_sync(0xffffffffu, mx, 1));
            mx = fmaxf(mx, __shfl_xor_sync(0xffffffffu, mx, 2));
            float m_old = smM[r];
            float m_new = fmaxf(m_old, mx);
            float sum = 0.0f;
            #pragma unroll
            for (int q = 0; q < 16; q++) {
                v[q] = __expf(v[q] - m_new);
                sum += v[q];
            }
            sum += __shfl_xor_sync(0xffffffffu, sum, 1);
            sum += __shfl_xor_sync(0xffffffffu, sum, 2);
            float fac = __expf(m_old - m_new);
            if (seg == 0) {
                smM[r] = m_new;
                smL[r] = smL[r] * fac + sum;
                smF[r] = fac;
            }
            #pragma unroll
            for (int q = 0; q < 4; q++) {
                float4 t = make_float4(to_tf32(v[q * 4 + 0]), to_tf32(v[q * 4 + 1]),
                                       to_tf32(v[q * 4 + 2]), to_tf32(v[q * 4 + 3]));
                *(float4*)&Ps[r * 68 + seg * 16 + (q << 2)] = t;
            }
        }

        // ---- store V (tf32, pitch 136) ----
        #pragma unroll
        for (int it = 0; it < 8; it++) {
            int row = trow + (it << 3);
            *(float4*)&KVs[row * 136 + tc4] = to_tf32_4(vreg[it]);
        }

        // ---- prefetch K(kb+1): in flight through sync(D)+PV+sync(A) ----
        if (kb + 1 < nkb) {
            #pragma unroll
            for (int it = 0; it < 8; it++) {
                int row = trow + (it << 3);
                kreg[it] = *(const float4*)(Kg + (size_t)(k0 + 64 + row) * DKV_ + tc4);
            }
        }
        __syncthreads();   // (D) V + exp(P) + smF ready

        // ---- rescale O accum, then O += P V via mma ----
        {
            int r0 = wm * 16 + rr;
            float f0 = smF[r0];
            float f1 = smF[r0 + 8];
            #pragma unroll
            for (int j = 0; j < 8; j++) {
                o[j][0] *= f0; o[j][1] *= f0;
                o[j][2] *= f1; o[j][3] *= f1;
            }
            const float* pbase = &Ps[(wm * 16 + rr) * 68];
            #pragma unroll
            for (int ks = 0; ks < 8; ks++) {
                const int c = (ks << 3) + m_;
                const float* pp = pbase + c;
                float4 a = make_float4(pp[0], pp[8 * 68], pp[4], pp[8 * 68 + 4]);
                const float* vbase = &KVs[c * 136 + wn * 64 + rr];
                #pragma unroll
                for (int j = 0; j < 8; j++) {
                    const float* vp = vbase + (j << 3);
                    float2 bfr = make_float2(vp[0], vp[4 * 136]);
                    mma_tf32(o[j], a, bfr);
                }
            }
        }
    }

    // ---- epilogue: normalize, write g_O ----
    {
        int r0 = wm * 16 + rr;
        int r1 = r0 + 8;
        float inv0 = 1.0f / smL[r0];
        float inv1 = 1.0f / smL[r1];
        float* op0 = g_O + (size_t)(b * L_ + q0 + r0) * D_ + h * DK_;
        float* op1 = g_O + (size_t)(b * L_ + q0 + r1) * D_ + h * DK_;
        #pragma unroll
        for (int j = 0; j < 8; j++) {
            int n = (wn * 8 + j) * 8 + (m_ << 1);
            *(float2*)(op0 + n) = make_float2(o[j][0] * inv0, o[j][1] * inv0);
            *(float2*)(op1 + n) = make_float2(o[j][2] * inv1, o[j][3] * inv1);
        }
    }
}

// ---------------- launch ----------------
extern "C" void kernel_launch(void* const* d_in, const int* in_sizes, int n_in,
                              void* d_out, int out_size) {
    const float* query = (const float*)d_in[0];
    const float* key_t = (const float*)d_in[1];
    const float* value = (const float*)d_in[2];
    // d_in[3] = mask (causal tril; unused)
    const float* Wq = (const float*)d_in[4];
    const float* Wk = (const float*)d_in[5];
    const float* Wv = (const float*)d_in[6];
    const float* Wo = (const float*)d_in[7];
    float* out = (float*)d_out;

    float *Qb, *Kb, *Vb, *Ob;
    cudaGetSymbolAddress((void**)&Qb, g_Q);
    cudaGetSymbolAddress((void**)&Kb, g_K);
    cudaGetSymbolAddress((void**)&Vb, g_V);
    cudaGetSymbolAddress((void**)&Ob, g_O);

    cudaFuncSetAttribute(gemm_tf32_kernel, cudaFuncAttributeMaxDynamicSharedMemorySize,
                         GEMM_SMEM_BYTES);
    cudaFuncSetAttribute(attn_kernel, cudaFuncAttributeMaxDynamicSharedMemorySize,
                         ATTN_SMEM_BYTES);

    rope_table_kernel<<<512, 256>>>();

    gemm_tf32_kernel<<<dim3(D_ / 128, M_ / 128), 512, GEMM_SMEM_BYTES>>>(query, Wq, Qb, M_, D_, D_);
    gemm_tf32_kernel<<<dim3(DKV_ / 128, M_ / 128), 512, GEMM_SMEM_BYTES>>>(key_t, Wk, Kb, M_, DKV_, D_);
    gemm_tf32_kernel<<<dim3(DKV_ / 128, M_ / 128), 512, GEMM_SMEM_BYTES>>>(value, Wv, Vb, M_, DKV_, D_);

    rope_apply_kernel<<<(M_ * H_ * 64) / 256, 256>>>(Qb, H_, D_);
    rope_apply_kernel<<<(M_ * KVH_ * 64) / 256, 256>>>(Kb, KVH_, DKV_);

    attn_kernel<<<dim3(L_ / 64, H_, B_), 256, ATTN_SMEM_BYTES>>>();

    gemm_tf32_kernel<<<dim3(D_ / 128, M_ / 128), 512, GEMM_SMEM_BYTES>>>(Ob, Wo, out, M_, D_, D_);
}

// round 11
// speedup vs baseline: 1.0842x; 1.0842x over previous
#include <cuda_runtime.h>
#include <cuda_bf16.h>
#include <math.h>
#include <stdint.h>

// Problem constants
#define B_    2
#define L_    2048
#define D_    2048
#define H_    16
#define KVH_  4
#define DK_   128
#define DKV_  512            // KVH_ * DK_
#define M_    (B_ * L_)      // 4096 rows
#define CAPV  50.0f

// ---------------- scratch (static device globals; no allocation) ----------------
static __device__ float g_Q[(size_t)M_ * D_];
static __device__ float g_K[(size_t)M_ * DKV_];
static __device__ float g_V[(size_t)M_ * DKV_];
static __device__ float g_O[(size_t)M_ * D_];
static __device__ float g_cos[L_ * 64];
static __device__ float g_sin[L_ * 64];

// ---------------- RoPE table ----------------
__global__ void rope_table_kernel() {
    int idx = blockIdx.x * blockDim.x + threadIdx.x;
    if (idx >= L_ * 64) return;
    int pos = idx >> 6;
    int i   = idx & 63;
    float expnt = (float)(2 * i) / 128.0f;
    float invf  = powf(10000.0f, -expnt);
    float f     = (float)pos * invf;
    g_cos[idx] = cosf(f);
    g_sin[idx] = sinf(f);
}

// ---------------- RoPE apply + clip (in place) ----------------
__global__ void rope_apply_kernel(float* __restrict__ X, int heads, int rowstride) {
    int idx   = blockIdx.x * blockDim.x + threadIdx.x;
    int total = M_ * heads * 64;
    if (idx >= total) return;
    int i   = idx & 63;
    int t   = idx >> 6;
    int h   = t % heads;
    int row = t / heads;
    int pos = row & (L_ - 1);
    float c = g_cos[(pos << 6) + i];
    float s = g_sin[(pos << 6) + i];
    float* p = X + (size_t)row * rowstride + h * DK_ + i;
    float x1 = p[0], x2 = p[64];
    float o1 = x1 * c - x2 * s;
    float o2 = x1 * s + x2 * c;
    p[0]  = fminf(fmaxf(o1, -CAPV), CAPV);
    p[64] = fminf(fmaxf(o2, -CAPV), CAPV);
}

// ---------------- tf32 / mma / ldmatrix helpers ----------------
__device__ __forceinline__ float to_tf32(float x) {
    float r;
    asm("cvt.rna.tf32.f32 %0, %1;" : "=f"(r) : "f"(x));
    return r;
}
__device__ __forceinline__ float4 to_tf32_4(float4 v) {
    return make_float4(to_tf32(v.x), to_tf32(v.y), to_tf32(v.z), to_tf32(v.w));
}
__device__ __forceinline__ uint32_t smem_u32(const void* p) {
    return (uint32_t)__cvta_generic_to_shared(p);
}
// ldmatrix x4: 4 8x8-b16 quadrants; for tf32, each quadrant = 8 rows x 4 fp32 words.
__device__ __forceinline__ void ldsm4(uint32_t addr, uint32_t* r) {
    asm volatile("ldmatrix.sync.aligned.m8n8.x4.shared.b16 {%0,%1,%2,%3}, [%4];"
        : "=r"(r[0]), "=r"(r[1]), "=r"(r[2]), "=r"(r[3]) : "r"(addr));
}
__device__ __forceinline__ void mma_tf32_u(float* c, const uint32_t* a,
                                           uint32_t b0, uint32_t b1) {
    asm volatile(
        "mma.sync.aligned.m16n8k8.row.col.f32.tf32.tf32.f32 "
        "{%0,%1,%2,%3}, {%4,%5,%6,%7}, {%8,%9}, {%0,%1,%2,%3};"
        : "+f"(c[0]), "+f"(c[1]), "+f"(c[2]), "+f"(c[3])
        : "r"(a[0]), "r"(a[1]), "r"(a[2]), "r"(a[3]), "r"(b0), "r"(b1));
}
__device__ __forceinline__ void mma_tf32(float* c, const float4& a, const float2& b) {
    const unsigned* A  = reinterpret_cast<const unsigned*>(&a);
    const unsigned* Bv = reinterpret_cast<const unsigned*>(&b);
    asm volatile(
        "mma.sync.aligned.m16n8k8.row.col.f32.tf32.tf32.f32 "
        "{%0,%1,%2,%3}, {%4,%5,%6,%7}, {%8,%9}, {%0,%1,%2,%3};"
        : "+f"(c[0]), "+f"(c[1]), "+f"(c[2]), "+f"(c[3])
        : "r"(A[0]), "r"(A[1]), "r"(A[2]), "r"(A[3]), "r"(Bv[0]), "r"(Bv[1]));
}

// ---------------- tf32 NT GEMM, double-buffered, ldmatrix mainloop --------------
// C[M,N] = A[M,K] * Bw[N,K]^T.  BM=BN=128, BK=32, 256 threads (8 warps 2x4),
// warp tile 64x32. Tiles row-major pitch 36 (=4 mod 32): STS.128 stores and
// LDSM quadrants both conflict-free. Fragment loads: ldmatrix.x4
// (A m16k8 frag = 1 LDSM; B frag-pair = 1 LDSM). 24 LDSM per 64 mmas per warp.
#define GEMM_TILE_F   (128 * 36)
#define GEMM_SMEM_BYTES (2 * 2 * GEMM_TILE_F * 4)  // 73728

__global__ void __launch_bounds__(256) gemm_tf32_kernel(
    const float* __restrict__ A, const float* __restrict__ Bw,
    float* __restrict__ C, int M, int N, int K)
{
    extern __shared__ float smg[];
    float* sA = smg;                       // [2][128*36]
    float* sB = smg + 2 * GEMM_TILE_F;     // [2][128*36]

    const int tid    = threadIdx.x;
    const int lane   = tid & 31;
    const int wid    = tid >> 5;
    const int warp_m = wid & 1;
    const int warp_n = wid >> 1;
    const int bm     = blockIdx.y << 7;
    const int bn     = blockIdx.x << 7;

    // ldmatrix per-lane quadrant coords
    const int qd     = lane >> 3;
    const int arow_l = ((qd & 1) << 3) + (lane & 7);
    const int acol_l = (qd >> 1) << 2;
    const int brow_l = ((qd >> 1) << 3) + (lane & 7);
    const int bcol_l = (qd & 1) << 2;

    const uint32_t smb = smem_u32(smg);
    const uint32_t aoff = smb + 4 * ((warp_m * 64 + arow_l) * 36 + acol_l);
    const uint32_t boff = smb + 4 * (2 * GEMM_TILE_F + (warp_n * 32 + brow_l) * 36 + bcol_l);

    float acc[4][4][4];
    #pragma unroll
    for (int mt = 0; mt < 4; mt++)
        #pragma unroll
        for (int nt = 0; nt < 4; nt++)
            #pragma unroll
            for (int r = 0; r < 4; r++) acc[mt][nt][r] = 0.0f;

    float4 avA[4], avB[4];
    #pragma unroll
    for (int i = 0; i < 4; i++) {
        int idx = tid + (i << 8);
        int row = idx >> 3;
        int c4  = idx & 7;
        avA[i] = *(const float4*)(A  + (size_t)(bm + row) * K + (c4 << 2));
        avB[i] = *(const float4*)(Bw + (size_t)(bn + row) * K + (c4 << 2));
    }

    auto store_stage = [&](int s) {
        float* dA = sA + s * GEMM_TILE_F;
        float* dB = sB + s * GEMM_TILE_F;
        #pragma unroll
        for (int i = 0; i < 4; i++) {
            int idx = tid + (i << 8);
            int row = idx >> 3;
            int c4  = idx & 7;
            *(float4*)&dA[row * 36 + (c4 << 2)] = to_tf32_4(avA[i]);
            *(float4*)&dB[row * 36 + (c4 << 2)] = to_tf32_4(avB[i]);
        }
    };

    store_stage(0);
    __syncthreads();

    const int stages = K >> 5;
    for (int kt = 0; kt < stages; kt++) {
        const int s = kt & 1;
        const bool has_next = (kt + 1) < stages;
        if (has_next) {
            int koff = (kt + 1) << 5;
            #pragma unroll
            for (int i = 0; i < 4; i++) {
                int idx = tid + (i << 8);
                int row = idx >> 3;
                int c4  = idx & 7;
                avA[i] = *(const float4*)(A  + (size_t)(bm + row) * K + koff + (c4 << 2));
                avB[i] = *(const float4*)(Bw + (size_t)(bn + row) * K + koff + (c4 << 2));
            }
        }

        const uint32_t aS = aoff + s * (GEMM_TILE_F * 4);
        const uint32_t bS = boff + s * (GEMM_TILE_F * 4);
        #pragma unroll
        for (int ks = 0; ks < 4; ks++) {
            const uint32_t kb4 = (uint32_t)(ks << 5);   // ks*8 words
            uint32_t af[4][4];
            #pragma unroll
            for (int mt = 0; mt < 4; mt++)
                ldsm4(aS + mt * (16 * 36 * 4) + kb4, af[mt]);
            uint32_t bf0[4], bf1[4];
            ldsm4(bS + kb4, bf0);                       // frags nt0, nt1
            ldsm4(bS + (16 * 36 * 4) + kb4, bf1);       // frags nt2, nt3
            #pragma unroll
            for (int mt = 0; mt < 4; mt++) {
                mma_tf32_u(acc[mt][0], af[mt], bf0[0], bf0[1]);
                mma_tf32_u(acc[mt][1], af[mt], bf0[2], bf0[3]);
                mma_tf32_u(acc[mt][2], af[mt], bf1[0], bf1[1]);
                mma_tf32_u(acc[mt][3], af[mt], bf1[2], bf1[3]);
            }
        }

        if (has_next) store_stage(s ^ 1);
        __syncthreads();
    }

    const int g   = lane >> 2;
    const int tig = lane & 3;
    #pragma unroll
    for (int mt = 0; mt < 4; mt++) {
        int r0 = bm + warp_m * 64 + mt * 16 + g;
        #pragma unroll
        for (int nt = 0; nt < 4; nt++) {
            int c = bn + warp_n * 32 + nt * 8 + (tig << 1);
            *(float2*)(&C[(size_t)r0 * N + c])       = make_float2(acc[mt][nt][0], acc[mt][nt][1]);
            *(float2*)(&C[(size_t)(r0 + 8) * N + c]) = make_float2(acc[mt][nt][2], acc[mt][nt][3]);
        }
    }
}

// ---------------- tf32 tensor-core flash attention (causal) ----------------
// R5 structure; S-loop A/B frags and PV P-frags via ldmatrix. V B-frags stay
// scalar (V is kv-major; frag rows not contiguous).
//   Qs  float[64*132] @0, KVs float[64*136] @8448 (K pitch 132 / V pitch 136),
//   Ps  float[64*68] @17152, smM/L/F @21504.
#define ATTN_SMEM_BYTES 86784

__global__ void __launch_bounds__(256, 2) attn_kernel() {
    extern __shared__ float smf[];
    float* Qs  = smf;
    float* KVs = smf + 8448;
    float* Ps  = smf + 17152;
    float* smM = smf + 21504;
    float* smL = smM + 64;
    float* smF = smL + 64;

    const int tid  = threadIdx.x;
    const int lane = tid & 31;
    const int wid  = tid >> 5;
    const int wm   = wid & 3;
    const int wn   = wid >> 2;
    const int m_   = lane & 3;
    const int rr   = lane >> 2;

    const int qb  = blockIdx.x;
    const int h   = blockIdx.y;
    const int b   = blockIdx.z;
    const int q0  = qb << 6;
    const int kvh = h >> 2;

    const float* Qg = g_Q + (size_t)(b * L_ + q0) * D_ + h * DK_;
    const float* Kg = g_K + (size_t)(b * L_) * DKV_ + kvh * DK_;
    const float* Vg = g_V + (size_t)(b * L_) * DKV_ + kvh * DK_;

    // ldmatrix per-lane quadrant coords
    const int qd     = lane >> 3;
    const int arow_l = ((qd & 1) << 3) + (lane & 7);
    const int acol_l = (qd >> 1) << 2;
    const int brow_l = ((qd >> 1) << 3) + (lane & 7);
    const int bcol_l = (qd & 1) << 2;
    const uint32_t smb = smem_u32(smf);
    const uint32_t aQ = smb + 4 * ((wm * 16 + arow_l) * 132 + acol_l);
    const uint32_t bK = smb + 4 * (8448 + (wn * 32 + brow_l) * 132 + bcol_l);
    const uint32_t aP = smb + 4 * (17152 + (wm * 16 + arow_l) * 68 + acol_l);

    #pragma unroll
    for (int it = 0; it < 8; it++) {
        int idx = tid + (it << 8);
        int row = idx >> 5;
        int c4  = (idx & 31) << 2;
        float4 v = *(const float4*)(Qg + (size_t)row * D_ + c4);
        *(float4*)&Qs[row * 132 + c4] = to_tf32_4(v);
    }
    if (tid < 64) { smM[tid] = -1e30f; smL[tid] = 0.0f; }

    float o[8][4];
    #pragma unroll
    for (int j = 0; j < 8; j++)
        #pragma unroll
        for (int r = 0; r < 4; r++) o[j][r] = 0.0f;

    const float scale = 0.08838834764831845f;
    const int nkb = qb + 1;

    for (int kb = 0; kb < nkb; kb++) {
        const int k0 = kb << 6;
        __syncthreads();
        #pragma unroll
        for (int it = 0; it < 8; it++) {
            int idx = tid + (it << 8);
            int row = idx >> 5;
            int c4  = (idx & 31) << 2;
            float4 v = *(const float4*)(Kg + (size_t)(k0 + row) * DKV_ + c4);
            *(float4*)&KVs[row * 132 + c4] = to_tf32_4(v);
        }
        __syncthreads();

        // ---- S = Q K^T via mma (ldmatrix frags) ----
        {
            float s4[4][4];
            #pragma unroll
            for (int j = 0; j < 4; j++)
                #pragma unroll
                for (int r = 0; r < 4; r++) s4[j][r] = 0.0f;

            #pragma unroll
            for (int ks = 0; ks < 16; ks++) {
                const uint32_t kb4 = (uint32_t)(ks << 5);
                uint32_t af[4], bf0[4], bf1[4];
                ldsm4(aQ + kb4, af);
                ldsm4(bK + kb4, bf0);                     // kv frags 0,1
                ldsm4(bK + (16 * 132 * 4) + kb4, bf1);    // kv frags 2,3
                mma_tf32_u(s4[0], af, bf0[0], bf0[1]);
                mma_tf32_u(s4[1], af, bf0[2], bf0[3]);
                mma_tf32_u(s4[2], af, bf1[0], bf1[1]);
                mma_tf32_u(s4[3], af, bf1[2], bf1[3]);
            }

            int r0 = wm * 16 + rr;
            int r1 = r0 + 8;
            #pragma unroll
            for (int j = 0; j < 4; j++) {
                int c0 = (wn * 4 + j) * 8 + (m_ << 1);
                float v00 = s4[j][0] * scale, v01 = s4[j][1] * scale;
                float v10 = s4[j][2] * scale, v11 = s4[j][3] * scale;
                if (k0 + c0     > q0 + r0) v00 = -1e30f;
                if (k0 + c0 + 1 > q0 + r0) v01 = -1e30f;
                if (k0 + c0     > q0 + r1) v10 = -1e30f;
                if (k0 + c0 + 1 > q0 + r1) v11 = -1e30f;
                *(float2*)&Ps[r0 * 68 + c0] = make_float2(v00, v01);
                *(float2*)&Ps[r1 * 68 + c0] = make_float2(v10, v11);
            }
        }
        __syncthreads();

        // ---- V tile (pitch 136) ----
        #pragma unroll
        for (int it = 0; it < 8; it++) {
            int idx = tid + (it << 8);
            int row = idx >> 5;
            int c4  = (idx & 31) << 2;
            float4 v = *(const float4*)(Vg + (size_t)(k0 + row) * DKV_ + c4);
            *(float4*)&KVs[row * 136 + c4] = to_tf32_4(v);
        }

        // ---- online softmax: 4 threads per row ----
        {
            int r   = tid >> 2;
            int seg = tid & 3;
            float v[16];
            #pragma unroll
            for (int q = 0; q < 4; q++) {
                float4 t = *(float4*)&Ps[r * 68 + seg * 16 + (q << 2)];
                v[q * 4 + 0] = t.x; v[q * 4 + 1] = t.y;
                v[q * 4 + 2] = t.z; v[q * 4 + 3] = t.w;
            }
            float mx = v[0];
            #pragma unroll
            for (int q = 1; q < 16; q++) mx = fmaxf(mx, v[q]);
            mx = fmaxf(mx, __shfl_xor_sync(0xffffffffu, mx, 1));
            mx = fmaxf(mx, __shfl_xor_sync(0xffffffffu, mx, 2));
            float m_old = smM[r];
            float m_new = fmaxf(m_old, mx);
            float sum = 0.0f;
            #pragma unroll
            for (int q = 0; q < 16; q++) {
                v[q] = __expf(v[q] - m_new);
                sum += v[q];
            }
            sum += __shfl_xor_sync(0xffffffffu, sum, 1);
            sum += __shfl_xor_sync(0xffffffffu, sum, 2);
            float fac = __expf(m_old - m_new);
            if (seg == 0) {
                smM[r] = m_new;
                smL[r] = smL[r] * fac + sum;
                smF[r] = fac;
            }
            #pragma unroll
            for (int q = 0; q < 4; q++) {
                float4 t = make_float4(to_tf32(v[q * 4 + 0]), to_tf32(v[q * 4 + 1]),
                                       to_tf32(v[q * 4 + 2]), to_tf32(v[q * 4 + 3]));
                *(float4*)&Ps[r * 68 + seg * 16 + (q << 2)] = t;
            }
        }
        __syncthreads();

        // ---- rescale O accum, then O += P V via mma ----
        {
            int r0 = wm * 16 + rr;
            float f0 = smF[r0];
            float f1 = smF[r0 + 8];
            #pragma unroll
            for (int j = 0; j < 8; j++) {
                o[j][0] *= f0; o[j][1] *= f0;
                o[j][2] *= f1; o[j][3] *= f1;
            }
            #pragma unroll
            for (int ks = 0; ks < 8; ks++) {
                const int c = (ks << 3) + m_;
                uint32_t pf[4];
                ldsm4(aP + (uint32_t)(ks << 5), pf);
                const float* vbase = &KVs[c * 136 + wn * 64 + rr];
                #pragma unroll
                for (int j = 0; j < 8; j++) {
                    const float* vp = vbase + (j << 3);
                    mma_tf32_u(o[j], pf,
                               __float_as_uint(vp[0]), __float_as_uint(vp[4 * 136]));
                }
            }
        }
    }

    // ---- epilogue: normalize, write g_O ----
    {
        int r0 = wm * 16 + rr;
        int r1 = r0 + 8;
        float inv0 = 1.0f / smL[r0];
        float inv1 = 1.0f / smL[r1];
        float* op0 = g_O + (size_t)(b * L_ + q0 + r0) * D_ + h * DK_;
        float* op1 = g_O + (size_t)(b * L_ + q0 + r1) * D_ + h * DK_;
        #pragma unroll
        for (int j = 0; j < 8; j++) {
            int n = (wn * 8 + j) * 8 + (m_ << 1);
            *(float2*)(op0 + n) = make_float2(o[j][0] * inv0, o[j][1] * inv0);
            *(float2*)(op1 + n) = make_float2(o[j][2] * inv1, o[j][3] * inv1);
        }
    }
}

// ---------------- launch ----------------
extern "C" void kernel_launch(void* const* d_in, const int* in_sizes, int n_in,
                              void* d_out, int out_size) {
    const float* query = (const float*)d_in[0];
    const float* key_t = (const float*)d_in[1];
    const float* value = (const float*)d_in[2];
    // d_in[3] = mask (causal tril; unused)
    const float* Wq = (const float*)d_in[4];
    const float* Wk = (const float*)d_in[5];
    const float* Wv = (const float*)d_in[6];
    const float* Wo = (const float*)d_in[7];
    float* out = (float*)d_out;

    float *Qb, *Kb, *Vb, *Ob;
    cudaGetSymbolAddress((void**)&Qb, g_Q);
    cudaGetSymbolAddress((void**)&Kb, g_K);
    cudaGetSymbolAddress((void**)&Vb, g_V);
    cudaGetSymbolAddress((void**)&Ob, g_O);

    cudaFuncSetAttribute(gemm_tf32_kernel, cudaFuncAttributeMaxDynamicSharedMemorySize,
                         GEMM_SMEM_BYTES);
    cudaFuncSetAttribute(attn_kernel, cudaFuncAttributeMaxDynamicSharedMemorySize,
                         ATTN_SMEM_BYTES);

    rope_table_kernel<<<512, 256>>>();

    gemm_tf32_kernel<<<dim3(D_ / 128, M_ / 128), 256, GEMM_SMEM_BYTES>>>(query, Wq, Qb, M_, D_, D_);
    gemm_tf32_kernel<<<dim3(DKV_ / 128, M_ / 128), 256, GEMM_SMEM_BYTES>>>(key_t, Wk, Kb, M_, DKV_, D_);
    gemm_tf32_kernel<<<dim3(DKV_ / 128, M_ / 128), 256, GEMM_SMEM_BYTES>>>(value, Wv, Vb, M_, DKV_, D_);

    rope_apply_kernel<<<(M_ * H_ * 64) / 256, 256>>>(Qb, H_, D_);
    rope_apply_kernel<<<(M_ * KVH_ * 64) / 256, 256>>>(Kb, KVH_, DKV_);

    attn_kernel<<<dim3(L_ / 64, H_, B_), 256, ATTN_SMEM_BYTES>>>();

    gemm_tf32_kernel<<<dim3(D_ / 128, M_ / 128), 256, GEMM_SMEM_BYTES>>>(Ob, Wo, out, M_, D_, D_);
}

// round 12
// speedup vs baseline: 1.3735x; 1.2669x over previous
#include <cuda_runtime.h>
#include <cuda_fp16.h>
#include <math.h>
#include <stdint.h>

// Problem constants
#define B_    2
#define L_    2048
#define D_    2048
#define H_    16
#define KVH_  4
#define DK_   128
#define DKV_  512            // KVH_ * DK_
#define M_    (B_ * L_)      // 4096 rows
#define CAPV  50.0f

// ---------------- scratch (static device globals; no allocation) ----------------
static __device__ __half g_Xq[(size_t)M_ * D_];
static __device__ __half g_Xk[(size_t)M_ * D_];
static __device__ __half g_Xv[(size_t)M_ * D_];
static __device__ __half g_Wq[(size_t)D_ * D_];
static __device__ __half g_Wk[(size_t)DKV_ * D_];
static __device__ __half g_Wv[(size_t)DKV_ * D_];
static __device__ __half g_Wo[(size_t)D_ * D_];
static __device__ __half g_Q[(size_t)M_ * D_];
static __device__ __half g_K[(size_t)M_ * DKV_];
static __device__ __half g_V[(size_t)M_ * DKV_];
static __device__ __half g_O[(size_t)M_ * D_];
static __device__ float  g_cos[L_ * 64];
static __device__ float  g_sin[L_ * 64];

// ---------------- fp32 -> fp16 convert ----------------
__global__ void f32_to_f16_kernel(const float* __restrict__ src,
                                  __half* __restrict__ dst, int n4) {
    int i = blockIdx.x * blockDim.x + threadIdx.x;
    if (i >= n4) return;
    float4 v = ((const float4*)src)[i];
    __half2 a = __floats2half2_rn(v.x, v.y);
    __half2 b = __floats2half2_rn(v.z, v.w);
    uint2 u;
    u.x = *(uint32_t*)&a;
    u.y = *(uint32_t*)&b;
    ((uint2*)dst)[i] = u;
}

// ---------------- RoPE table ----------------
__global__ void rope_table_kernel() {
    int idx = blockIdx.x * blockDim.x + threadIdx.x;
    if (idx >= L_ * 64) return;
    int pos = idx >> 6;
    int i   = idx & 63;
    float expnt = (float)(2 * i) / 128.0f;
    float invf  = powf(10000.0f, -expnt);
    float f     = (float)pos * invf;
    g_cos[idx] = cosf(f);
    g_sin[idx] = sinf(f);
}

// ---------------- RoPE apply + clip (in place, fp16) ----------------
__global__ void rope_apply_kernel(__half* __restrict__ X, int heads, int rowstride) {
    int idx   = blockIdx.x * blockDim.x + threadIdx.x;
    int total = M_ * heads * 64;
    if (idx >= total) return;
    int i   = idx & 63;
    int t   = idx >> 6;
    int h   = t % heads;
    int row = t / heads;
    int pos = row & (L_ - 1);
    float c = g_cos[(pos << 6) + i];
    float s = g_sin[(pos << 6) + i];
    __half* p = X + (size_t)row * rowstride + h * DK_ + i;
    float x1 = __half2float(p[0]), x2 = __half2float(p[64]);
    float o1 = x1 * c - x2 * s;
    float o2 = x1 * s + x2 * c;
    p[0]  = __float2half_rn(fminf(fmaxf(o1, -CAPV), CAPV));
    p[64] = __float2half_rn(fminf(fmaxf(o2, -CAPV), CAPV));
}

// ---------------- mma / ldmatrix / cp.async helpers ----------------
__device__ __forceinline__ uint32_t smem_u32(const void* p) {
    return (uint32_t)__cvta_generic_to_shared(p);
}
__device__ __forceinline__ void ldsm4(uint32_t addr, uint32_t* r) {
    asm volatile("ldmatrix.sync.aligned.m8n8.x4.shared.b16 {%0,%1,%2,%3}, [%4];"
        : "=r"(r[0]), "=r"(r[1]), "=r"(r[2]), "=r"(r[3]) : "r"(addr));
}
__device__ __forceinline__ void ldsm4t(uint32_t addr, uint32_t* r) {
    asm volatile("ldmatrix.sync.aligned.m8n8.x4.trans.shared.b16 {%0,%1,%2,%3}, [%4];"
        : "=r"(r[0]), "=r"(r[1]), "=r"(r[2]), "=r"(r[3]) : "r"(addr));
}
__device__ __forceinline__ void mma_f16(float* c, const uint32_t* a,
                                        uint32_t b0, uint32_t b1) {
    asm volatile(
        "mma.sync.aligned.m16n8k16.row.col.f32.f16.f16.f32 "
        "{%0,%1,%2,%3}, {%4,%5,%6,%7}, {%8,%9}, {%0,%1,%2,%3};"
        : "+f"(c[0]), "+f"(c[1]), "+f"(c[2]), "+f"(c[3])
        : "r"(a[0]), "r"(a[1]), "r"(a[2]), "r"(a[3]), "r"(b0), "r"(b1));
}
__device__ __forceinline__ void cp16(uint32_t smem_dst, const void* gsrc) {
    asm volatile("cp.async.ca.shared.global [%0], [%1], 16;" :: "r"(smem_dst), "l"(gsrc));
}
__device__ __forceinline__ void cp_commit() {
    asm volatile("cp.async.commit_group;");
}
template <int N>
__device__ __forceinline__ void cp_wait() {
    asm volatile("cp.async.wait_group %0;" :: "n"(N));
}
__device__ __forceinline__ uint32_t packh2(float a, float b) {
    __half2 h = __floats2half2_rn(a, b);
    return *(uint32_t*)&h;
}

// ---------------- fp16 NT GEMM, cp.async double-buffered, ldmatrix ----------------
// C[M,N] = A[M,K] * Bw[N,K]^T, fp16 in, fp32 accum. BM=BN=128, BK=64 (=128B rows),
// 256 threads (8 warps 2x4), warp tile 64x32, m16n8k16.
// smem rows: 64 fp16 data, pitch 72 fp16 (144B = 36 words, 4 mod 32 -> LDSM
// quadrant rows hit all 32 banks). Staging is raw-byte cp.async (no cvt).
#define GP_BYTES 144
#define GEMM_STAGE_BYTES (128 * GP_BYTES)          // 18432 per matrix
#define GEMM_SMEM_BYTES  (2 * 2 * GEMM_STAGE_BYTES)  // 73728

__global__ void __launch_bounds__(256, 2) gemm_f16_kernel(
    const __half* __restrict__ A, const __half* __restrict__ Bw,
    void* __restrict__ C, int M, int N, int K, int half_out)
{
    extern __shared__ char smc[];
    const uint32_t smb = smem_u32(smc);

    const int tid    = threadIdx.x;
    const int lane   = tid & 31;
    const int wid    = tid >> 5;
    const int warp_m = wid & 1;
    const int warp_n = wid >> 1;
    const int bm     = blockIdx.y << 7;
    const int bn     = blockIdx.x << 7;

    // ldmatrix quadrant lane coords
    const int qd   = lane >> 3;
    const int lr   = lane & 7;
    const int arow = ((qd & 1) << 3) + lr;           // A: q0/q2 rows 0-7, q1/q3 rows 8-15
    const uint32_t acol = (uint32_t)((qd >> 1) << 4); // A: q2/q3 k+8 (16B)
    const int brow = ((qd >> 1) << 3) + lr;          // B: q2/q3 n+8
    const uint32_t bcol = (uint32_t)((qd & 1) << 4);  // B: q1/q3 k+8

    const uint32_t aBase = smb + (uint32_t)(warp_m * 64 + arow) * GP_BYTES + acol;
    const uint32_t bBase = smb + 2 * GEMM_STAGE_BYTES
                         + (uint32_t)(warp_n * 32 + brow) * GP_BYTES + bcol;

    float acc[4][4][4];
    #pragma unroll
    for (int mt = 0; mt < 4; mt++)
        #pragma unroll
        for (int nt = 0; nt < 4; nt++)
            #pragma unroll
            for (int r = 0; r < 4; r++) acc[mt][nt][r] = 0.0f;

    auto issue_stage = [&](int kt, int s) {
        uint32_t dA = smb + s * GEMM_STAGE_BYTES;
        uint32_t dB = smb + (2 + s) * GEMM_STAGE_BYTES;
        const int koff = kt << 6;
        #pragma unroll
        for (int i = 0; i < 4; i++) {
            int idx = tid + (i << 8);        // 0..1023
            int row = idx >> 3;
            int ch  = idx & 7;               // 16B chunk within 128B row
            cp16(dA + row * GP_BYTES + (ch << 4),
                 A  + (size_t)(bm + row) * K + koff + (ch << 3));
            cp16(dB + row * GP_BYTES + (ch << 4),
                 Bw + (size_t)(bn + row) * K + koff + (ch << 3));
        }
        cp_commit();
    };

    const int T = K >> 6;
    issue_stage(0, 0);

    for (int kt = 0; kt < T; kt++) {
        const int s = kt & 1;
        cp_wait<0>();
        __syncthreads();                     // all compute(kt-1) done; stage kt ready
        if (kt + 1 < T) issue_stage(kt + 1, s ^ 1);

        const uint32_t aS = aBase + s * GEMM_STAGE_BYTES;
        const uint32_t bS = bBase + s * GEMM_STAGE_BYTES;
        #pragma unroll
        for (int ks = 0; ks < 4; ks++) {     // k16 steps within BK=64
            const uint32_t ko = (uint32_t)(ks << 5);   // 16 fp16 = 32B
            uint32_t af[4][4];
            #pragma unroll
            for (int mt = 0; mt < 4; mt++)
                ldsm4(aS + mt * (16 * GP_BYTES) + ko, af[mt]);
            uint32_t bf0[4], bf1[4];
            ldsm4(bS + ko, bf0);                        // n-frags 0,1
            ldsm4(bS + 16 * GP_BYTES + ko, bf1);        // n-frags 2,3
            #pragma unroll
            for (int mt = 0; mt < 4; mt++) {
                mma_f16(acc[mt][0], af[mt], bf0[0], bf0[1]);
                mma_f16(acc[mt][1], af[mt], bf0[2], bf0[3]);
                mma_f16(acc[mt][2], af[mt], bf1[0], bf1[1]);
                mma_f16(acc[mt][3], af[mt], bf1[2], bf1[3]);
            }
        }
        __syncthreads();                     // ensure reads done before reuse
    }

    const int g   = lane >> 2;
    const int tig = lane & 3;
    if (half_out) {
        __half* Ch = (__half*)C;
        #pragma unroll
        for (int mt = 0; mt < 4; mt++) {
            int r0 = bm + warp_m * 64 + mt * 16 + g;
            #pragma unroll
            for (int nt = 0; nt < 4; nt++) {
                int c = bn + warp_n * 32 + nt * 8 + (tig << 1);
                *(uint32_t*)(Ch + (size_t)r0 * N + c)       = packh2(acc[mt][nt][0], acc[mt][nt][1]);
                *(uint32_t*)(Ch + (size_t)(r0 + 8) * N + c) = packh2(acc[mt][nt][2], acc[mt][nt][3]);
            }
        }
    } else {
        float* Cf = (float*)C;
        #pragma unroll
        for (int mt = 0; mt < 4; mt++) {
            int r0 = bm + warp_m * 64 + mt * 16 + g;
            #pragma unroll
            for (int nt = 0; nt < 4; nt++) {
                int c = bn + warp_n * 32 + nt * 8 + (tig << 1);
                *(float2*)(Cf + (size_t)r0 * N + c)       = make_float2(acc[mt][nt][0], acc[mt][nt][1]);
                *(float2*)(Cf + (size_t)(r0 + 8) * N + c) = make_float2(acc[mt][nt][2], acc[mt][nt][3]);
            }
        }
    }
}

// ---------------- fp16 flash attention (causal) ----------------
// CTA: 64 q x 64 kv, DK=128. 256 threads, 8 warps (wm 0-3 m16, wn 0-1 kv/dk half).
// smem bytes: Qs [64x136 h] @0, KVs [64x136 h] @17408 (K then V), Ps f32 [64x68]
// @34816, Pf [64x72 h] @52224, smM/L/F @61440/61696/61952. Total 62208.
#define ATTN_SMEM_BYTES 62208
#define QK_PITCH 272        // 136 fp16
#define PF_PITCH 144        // 72 fp16

__global__ void __launch_bounds__(256, 2) attn_kernel() {
    extern __shared__ char smc[];
    float* Ps  = (float*)(smc + 34816);
    float* smM = (float*)(smc + 61440);
    float* smL = (float*)(smc + 61696);
    float* smF = (float*)(smc + 61952);
    const uint32_t smb = smem_u32(smc);

    const int tid  = threadIdx.x;
    const int lane = tid & 31;
    const int wid  = tid >> 5;
    const int wm   = wid & 3;
    const int wn   = wid >> 2;
    const int m_   = lane & 3;
    const int rr   = lane >> 2;

    const int qb  = blockIdx.x;
    const int h   = blockIdx.y;
    const int b   = blockIdx.z;
    const int q0  = qb << 6;
    const int kvh = h >> 2;

    const __half* Qg = g_Q + (size_t)(b * L_ + q0) * D_ + h * DK_;
    const __half* Kg = g_K + (size_t)(b * L_) * DKV_ + kvh * DK_;
    const __half* Vg = g_V + (size_t)(b * L_) * DKV_ + kvh * DK_;

    // ldmatrix lane coords
    const int qd = lane >> 3;
    const int lr = lane & 7;
    const int arow = ((qd & 1) << 3) + lr;
    const uint32_t acol = (uint32_t)((qd >> 1) << 4);
    const int brow = ((qd >> 1) << 3) + lr;
    const uint32_t bcol = (uint32_t)((qd & 1) << 4);

    const uint32_t aQ = smb + (uint32_t)(wm * 16 + arow) * QK_PITCH + acol;
    const uint32_t bK = smb + 17408 + (uint32_t)(wn * 32 + brow) * QK_PITCH + bcol;
    const uint32_t aP = smb + 52224 + (uint32_t)(wm * 16 + arow) * PF_PITCH + acol;
    // V (trans): q0/q1 = kv rows 0-7/8-15, q2/q3 = dk +8
    const uint32_t vB = smb + 17408 + (uint32_t)(((qd & 1) << 3) + lr) * QK_PITCH
                      + (uint32_t)(wn * 64 + ((qd >> 1) << 3)) * 2;

    // ---- stage Q (raw fp16 copy) ----
    #pragma unroll
    for (int i = 0; i < 4; i++) {
        int idx = tid + (i << 8);            // 0..1023
        int row = idx >> 4;
        int ch  = idx & 15;
        uint4 v = *(const uint4*)(Qg + (size_t)row * D_ + (ch << 3));
        *(uint4*)(smc + row * QK_PITCH + (ch << 4)) = v;
    }
    if (tid < 64) { smM[tid] = -1e30f; smL[tid] = 0.0f; }

    float o[8][4];
    #pragma unroll
    for (int j = 0; j < 8; j++)
        #pragma unroll
        for (int r = 0; r < 4; r++) o[j][r] = 0.0f;

    const float scale = 0.08838834764831845f;  // 1/sqrt(128)
    const int nkb = qb + 1;

    for (int kb = 0; kb < nkb; kb++) {
        const int k0 = kb << 6;
        __syncthreads();   // prev PV reads of KVs/Pf done; Q ready (iter 0)

        // ---- stage K ----
        #pragma unroll
        for (int i = 0; i < 4; i++) {
            int idx = tid + (i << 8);
            int row = idx >> 4;
            int ch  = idx & 15;
            uint4 v = *(const uint4*)(Kg + (size_t)(k0 + row) * DKV_ + (ch << 3));
            *(uint4*)(smc + 17408 + row * QK_PITCH + (ch << 4)) = v;
        }
        __syncthreads();

        // ---- S = Q K^T ----
        {
            float s4[4][4];
            #pragma unroll
            for (int j = 0; j < 4; j++)
                #pragma unroll
                for (int r = 0; r < 4; r++) s4[j][r] = 0.0f;

            #pragma unroll
            for (int ks = 0; ks < 8; ks++) {      // DK=128 -> 8 k16 steps
                const uint32_t ko = (uint32_t)(ks << 5);
                uint32_t af[4], bf0[4], bf1[4];
                ldsm4(aQ + ko, af);
                ldsm4(bK + ko, bf0);                       // kv frags 0,1
                ldsm4(bK + 16 * QK_PITCH + ko, bf1);       // kv frags 2,3
                mma_f16(s4[0], af, bf0[0], bf0[1]);
                mma_f16(s4[1], af, bf0[2], bf0[3]);
                mma_f16(s4[2], af, bf1[0], bf1[1]);
                mma_f16(s4[3], af, bf1[2], bf1[3]);
            }

            int r0 = wm * 16 + rr;
            int r1 = r0 + 8;
            #pragma unroll
            for (int j = 0; j < 4; j++) {
                int c0 = (wn * 4 + j) * 8 + (m_ << 1);
                float v00 = s4[j][0] * scale, v01 = s4[j][1] * scale;
                float v10 = s4[j][2] * scale, v11 = s4[j][3] * scale;
                if (k0 + c0     > q0 + r0) v00 = -1e30f;
                if (k0 + c0 + 1 > q0 + r0) v01 = -1e30f;
                if (k0 + c0     > q0 + r1) v10 = -1e30f;
                if (k0 + c0 + 1 > q0 + r1) v11 = -1e30f;
                *(float2*)&Ps[r0 * 68 + c0] = make_float2(v00, v01);
                *(float2*)&Ps[r1 * 68 + c0] = make_float2(v10, v11);
            }
        }
        __syncthreads();   // Ps ready; K reads done -> KVs reusable for V

        // ---- stage V (overwrites K buffer) ----
        #pragma unroll
        for (int i = 0; i < 4; i++) {
            int idx = tid + (i << 8);
            int row = idx >> 4;
            int ch  = idx & 15;
            uint4 v = *(const uint4*)(Vg + (size_t)(k0 + row) * DKV_ + (ch << 3));
            *(uint4*)(smc + 17408 + row * QK_PITCH + (ch << 4)) = v;
        }

        // ---- online softmax: 4 threads per row; exp -> Pf (fp16) ----
        {
            int r   = tid >> 2;
            int seg = tid & 3;
            float v[16];
            #pragma unroll
            for (int q = 0; q < 4; q++) {
                float4 t = *(float4*)&Ps[r * 68 + seg * 16 + (q << 2)];
                v[q * 4 + 0] = t.x; v[q * 4 + 1] = t.y;
                v[q * 4 + 2] = t.z; v[q * 4 + 3] = t.w;
            }
            float mx = v[0];
            #pragma unroll
            for (int q = 1; q < 16; q++) mx = fmaxf(mx, v[q]);
            mx = fmaxf(mx, __shfl_xor_sync(0xffffffffu, mx, 1));
            mx = fmaxf(mx, __shfl_xor_sync(0xffffffffu, mx, 2));
            float m_old = smM[r];
            float m_new = fmaxf(m_old, mx);
            float sum = 0.0f;
            #pragma unroll
            for (int q = 0; q < 16; q++) {
                v[q] = __expf(v[q] - m_new);
                sum += v[q];
            }
            sum += __shfl_xor_sync(0xffffffffu, sum, 1);
            sum += __shfl_xor_sync(0xffffffffu, sum, 2);
            float fac = __expf(m_old - m_new);
            if (seg == 0) {
                smM[r] = m_new;
                smL[r] = smL[r] * fac + sum;
                smF[r] = fac;
            }
            uint4 w0, w1;
            w0.x = packh2(v[0],  v[1]);  w0.y = packh2(v[2],  v[3]);
            w0.z = packh2(v[4],  v[5]);  w0.w = packh2(v[6],  v[7]);
            w1.x = packh2(v[8],  v[9]);  w1.y = packh2(v[10], v[11]);
            w1.z = packh2(v[12], v[13]); w1.w = packh2(v[14], v[15]);
            char* pd = smc + 52224 + r * PF_PITCH + seg * 32;
            *(uint4*)(pd)      = w0;
            *(uint4*)(pd + 16) = w1;
        }
        __syncthreads();   // V + Pf + smF ready

        // ---- rescale O, then O += P V (V via ldmatrix.trans) ----
        {
            int r0 = wm * 16 + rr;
            float f0 = smF[r0];
            float f1 = smF[r0 + 8];
            #pragma unroll
            for (int j = 0; j < 8; j++) {
                o[j][0] *= f0; o[j][1] *= f0;
                o[j][2] *= f1; o[j][3] *= f1;
            }
            #pragma unroll
            for (int ks = 0; ks < 4; ks++) {         // kv64 -> 4 k16 steps
                uint32_t pf[4];
                ldsm4(aP + (uint32_t)(ks << 5), pf);
                const uint32_t vk = vB + (uint32_t)(ks * 16 * QK_PITCH);
                #pragma unroll
                for (int t = 0; t < 4; t++) {        // 4 trans-LDSM = 8 dk frags
                    uint32_t vf[4];
                    ldsm4t(vk + (uint32_t)(t << 5), vf);
                    mma_f16(o[2 * t],     pf, vf[0], vf[1]);
                    mma_f16(o[2 * t + 1], pf, vf[2], vf[3]);
                }
            }
        }
    }

    // ---- epilogue: normalize, write g_O (fp16) ----
    {
        int r0 = wm * 16 + rr;
        int r1 = r0 + 8;
        float inv0 = 1.0f / smL[r0];
        float inv1 = 1.0f / smL[r1];
        __half* op0 = g_O + (size_t)(b * L_ + q0 + r0) * D_ + h * DK_;
        __half* op1 = g_O + (size_t)(b * L_ + q0 + r1) * D_ + h * DK_;
        #pragma unroll
        for (int j = 0; j < 8; j++) {
            int n = (wn * 8 + j) * 8 + (m_ << 1);
            *(uint32_t*)(op0 + n) = packh2(o[j][0] * inv0, o[j][1] * inv0);
            *(uint32_t*)(op1 + n) = packh2(o[j][2] * inv1, o[j][3] * inv1);
        }
    }
}

// ---------------- launch ----------------
extern "C" void kernel_launch(void* const* d_in, const int* in_sizes, int n_in,
                              void* d_out, int out_size) {
    const float* query = (const float*)d_in[0];
    const float* key_t = (const float*)d_in[1];
    const float* value = (const float*)d_in[2];
    // d_in[3] = mask (causal tril; unused)
    const float* Wq = (const float*)d_in[4];
    const float* Wk = (const float*)d_in[5];
    const float* Wv = (const float*)d_in[6];
    const float* Wo = (const float*)d_in[7];
    float* out = (float*)d_out;

    __half *Xq, *Xk, *Xv, *Whq, *Whk, *Whv, *Who, *Qb, *Kb, *Vb, *Ob;
    cudaGetSymbolAddress((void**)&Xq,  g_Xq);
    cudaGetSymbolAddress((void**)&Xk,  g_Xk);
    cudaGetSymbolAddress((void**)&Xv,  g_Xv);
    cudaGetSymbolAddress((void**)&Whq, g_Wq);
    cudaGetSymbolAddress((void**)&Whk, g_Wk);
    cudaGetSymbolAddress((void**)&Whv, g_Wv);
    cudaGetSymbolAddress((void**)&Who, g_Wo);
    cudaGetSymbolAddress((void**)&Qb,  g_Q);
    cudaGetSymbolAddress((void**)&Kb,  g_K);
    cudaGetSymbolAddress((void**)&Vb,  g_V);
    cudaGetSymbolAddress((void**)&Ob,  g_O);

    cudaFuncSetAttribute(gemm_f16_kernel, cudaFuncAttributeMaxDynamicSharedMemorySize,
                         GEMM_SMEM_BYTES);
    cudaFuncSetAttribute(attn_kernel, cudaFuncAttributeMaxDynamicSharedMemorySize,
                         ATTN_SMEM_BYTES);

    rope_table_kernel<<<512, 256>>>();

    // fp32 -> fp16 converts
    const int n4_big = (M_ * D_) / 4;       // 2,097,152
    const int n4_w   = (D_ * D_) / 4;       // 1,048,576
    const int n4_kv  = (DKV_ * D_) / 4;     //   262,144
    f32_to_f16_kernel<<<n4_big / 256, 256>>>(query, Xq, n4_big);
    f32_to_f16_kernel<<<n4_big / 256, 256>>>(key_t, Xk, n4_big);
    f32_to_f16_kernel<<<n4_big / 256, 256>>>(value, Xv, n4_big);
    f32_to_f16_kernel<<<n4_w / 256, 256>>>(Wq, Whq, n4_w);
    f32_to_f16_kernel<<<n4_kv / 256, 256>>>(Wk, Whk, n4_kv);
    f32_to_f16_kernel<<<n4_kv / 256, 256>>>(Wv, Whv, n4_kv);
    f32_to_f16_kernel<<<n4_w / 256, 256>>>(Wo, Who, n4_w);

    // Projections (fp16 in, fp16 out)
    gemm_f16_kernel<<<dim3(D_ / 128, M_ / 128), 256, GEMM_SMEM_BYTES>>>(
        Xq, Whq, Qb, M_, D_, D_, 1);
    gemm_f16_kernel<<<dim3(DKV_ / 128, M_ / 128), 256, GEMM_SMEM_BYTES>>>(
        Xk, Whk, Kb, M_, DKV_, D_, 1);
    gemm_f16_kernel<<<dim3(DKV_ / 128, M_ / 128), 256, GEMM_SMEM_BYTES>>>(
        Xv, Whv, Vb, M_, DKV_, D_, 1);

    // RoPE + clip (fp16)
    rope_apply_kernel<<<(M_ * H_ * 64) / 256, 256>>>(Qb, H_, D_);
    rope_apply_kernel<<<(M_ * KVH_ * 64) / 256, 256>>>(Kb, KVH_, DKV_);

    // Attention (fp16)
    attn_kernel<<<dim3(L_ / 64, H_, B_), 256, ATTN_SMEM_BYTES>>>();

    // Output projection (fp16 in, fp32 out)
    gemm_f16_kernel<<<dim3(D_ / 128, M_ / 128), 256, GEMM_SMEM_BYTES>>>(
        Ob, Who, out, M_, D_, D_, 0);
}

// round 13
// speedup vs baseline: 2.0792x; 1.5137x over previous
#include <cuda_runtime.h>
#include <cuda_fp16.h>
#include <math.h>
#include <stdint.h>

// Problem constants
#define B_    2
#define L_    2048
#define D_    2048
#define H_    16
#define KVH_  4
#define DK_   128
#define DKV_  512            // KVH_ * DK_
#define M_    (B_ * L_)      // 4096 rows
#define CAPV  50.0f

// ---------------- scratch (static device globals; no allocation) ----------------
static __device__ __half g_Xq[(size_t)M_ * D_];
static __device__ __half g_Xk[(size_t)M_ * D_];
static __device__ __half g_Xv[(size_t)M_ * D_];
static __device__ __half g_Wq[(size_t)D_ * D_];
static __device__ __half g_Wk[(size_t)DKV_ * D_];
static __device__ __half g_Wv[(size_t)DKV_ * D_];
static __device__ __half g_Wo[(size_t)D_ * D_];
static __device__ __half g_Q[(size_t)M_ * D_];
static __device__ __half g_K[(size_t)M_ * DKV_];
static __device__ __half g_V[(size_t)M_ * DKV_];
static __device__ __half g_O[(size_t)M_ * D_];
static __device__ float  g_cos[L_ * 64];
static __device__ float  g_sin[L_ * 64];

// ---------------- fp32 -> fp16 convert ----------------
__global__ void f32_to_f16_kernel(const float* __restrict__ src,
                                  __half* __restrict__ dst, int n4) {
    int i = blockIdx.x * blockDim.x + threadIdx.x;
    if (i >= n4) return;
    float4 v = ((const float4*)src)[i];
    __half2 a = __floats2half2_rn(v.x, v.y);
    __half2 b = __floats2half2_rn(v.z, v.w);
    uint2 u;
    u.x = *(uint32_t*)&a;
    u.y = *(uint32_t*)&b;
    ((uint2*)dst)[i] = u;
}

// ---------------- RoPE table ----------------
__global__ void rope_table_kernel() {
    int idx = blockIdx.x * blockDim.x + threadIdx.x;
    if (idx >= L_ * 64) return;
    int pos = idx >> 6;
    int i   = idx & 63;
    float expnt = (float)(2 * i) / 128.0f;
    float invf  = powf(10000.0f, -expnt);
    float f     = (float)pos * invf;
    g_cos[idx] = cosf(f);
    g_sin[idx] = sinf(f);
}

// ---------------- RoPE apply + clip (in place, fp16) ----------------
__global__ void rope_apply_kernel(__half* __restrict__ X, int heads, int rowstride) {
    int idx   = blockIdx.x * blockDim.x + threadIdx.x;
    int total = M_ * heads * 64;
    if (idx >= total) return;
    int i   = idx & 63;
    int t   = idx >> 6;
    int h   = t % heads;
    int row = t / heads;
    int pos = row & (L_ - 1);
    float c = g_cos[(pos << 6) + i];
    float s = g_sin[(pos << 6) + i];
    __half* p = X + (size_t)row * rowstride + h * DK_ + i;
    float x1 = __half2float(p[0]), x2 = __half2float(p[64]);
    float o1 = x1 * c - x2 * s;
    float o2 = x1 * s + x2 * c;
    p[0]  = __float2half_rn(fminf(fmaxf(o1, -CAPV), CAPV));
    p[64] = __float2half_rn(fminf(fmaxf(o2, -CAPV), CAPV));
}

// ---------------- mma / ldmatrix / cp.async helpers ----------------
__device__ __forceinline__ uint32_t smem_u32(const void* p) {
    return (uint32_t)__cvta_generic_to_shared(p);
}
__device__ __forceinline__ void ldsm4(uint32_t addr, uint32_t* r) {
    asm volatile("ldmatrix.sync.aligned.m8n8.x4.shared.b16 {%0,%1,%2,%3}, [%4];"
        : "=r"(r[0]), "=r"(r[1]), "=r"(r[2]), "=r"(r[3]) : "r"(addr));
}
__device__ __forceinline__ void ldsm4t(uint32_t addr, uint32_t* r) {
    asm volatile("ldmatrix.sync.aligned.m8n8.x4.trans.shared.b16 {%0,%1,%2,%3}, [%4];"
        : "=r"(r[0]), "=r"(r[1]), "=r"(r[2]), "=r"(r[3]) : "r"(addr));
}
__device__ __forceinline__ void mma_f16(float* c, const uint32_t* a,
                                        uint32_t b0, uint32_t b1) {
    asm volatile(
        "mma.sync.aligned.m16n8k16.row.col.f32.f16.f16.f32 "
        "{%0,%1,%2,%3}, {%4,%5,%6,%7}, {%8,%9}, {%0,%1,%2,%3};"
        : "+f"(c[0]), "+f"(c[1]), "+f"(c[2]), "+f"(c[3])
        : "r"(a[0]), "r"(a[1]), "r"(a[2]), "r"(a[3]), "r"(b0), "r"(b1));
}
__device__ __forceinline__ void cp16(uint32_t smem_dst, const void* gsrc) {
    asm volatile("cp.async.ca.shared.global [%0], [%1], 16;" :: "r"(smem_dst), "l"(gsrc));
}
__device__ __forceinline__ void cp_commit() {
    asm volatile("cp.async.commit_group;");
}
template <int N>
__device__ __forceinline__ void cp_wait() {
    asm volatile("cp.async.wait_group %0;" :: "n"(N));
}
__device__ __forceinline__ uint32_t packh2(float a, float b) {
    __half2 h = __floats2half2_rn(a, b);
    return *(uint32_t*)&h;
}

#define GP_BYTES 144   // smem pitch: 64 fp16 data + pad (36 words, 4 mod 32)

// ---------------- fp16 NT GEMM 128x128 (KV projections) ----------------
#define GEMM_STAGE_BYTES (128 * GP_BYTES)
#define GEMM_SMEM_BYTES  (2 * 2 * GEMM_STAGE_BYTES)  // 73728

__global__ void __launch_bounds__(256, 2) gemm_f16_kernel(
    const __half* __restrict__ A, const __half* __restrict__ Bw,
    void* __restrict__ C, int M, int N, int K, int half_out)
{
    extern __shared__ char smc[];
    const uint32_t smb = smem_u32(smc);

    const int tid    = threadIdx.x;
    const int lane   = tid & 31;
    const int wid    = tid >> 5;
    const int warp_m = wid & 1;
    const int warp_n = wid >> 1;
    const int bm     = blockIdx.y << 7;
    const int bn     = blockIdx.x << 7;

    const int qd   = lane >> 3;
    const int lr   = lane & 7;
    const int arow = ((qd & 1) << 3) + lr;
    const uint32_t acol = (uint32_t)((qd >> 1) << 4);
    const int brow = ((qd >> 1) << 3) + lr;
    const uint32_t bcol = (uint32_t)((qd & 1) << 4);

    const uint32_t aBase = smb + (uint32_t)(warp_m * 64 + arow) * GP_BYTES + acol;
    const uint32_t bBase = smb + 2 * GEMM_STAGE_BYTES
                         + (uint32_t)(warp_n * 32 + brow) * GP_BYTES + bcol;

    float acc[4][4][4];
    #pragma unroll
    for (int mt = 0; mt < 4; mt++)
        #pragma unroll
        for (int nt = 0; nt < 4; nt++)
            #pragma unroll
            for (int r = 0; r < 4; r++) acc[mt][nt][r] = 0.0f;

    auto issue_stage = [&](int kt, int s) {
        uint32_t dA = smb + s * GEMM_STAGE_BYTES;
        uint32_t dB = smb + (2 + s) * GEMM_STAGE_BYTES;
        const int koff = kt << 6;
        #pragma unroll
        for (int i = 0; i < 4; i++) {
            int idx = tid + (i << 8);
            int row = idx >> 3;
            int ch  = idx & 7;
            cp16(dA + row * GP_BYTES + (ch << 4),
                 A  + (size_t)(bm + row) * K + koff + (ch << 3));
            cp16(dB + row * GP_BYTES + (ch << 4),
                 Bw + (size_t)(bn + row) * K + koff + (ch << 3));
        }
        cp_commit();
    };

    const int T = K >> 6;
    issue_stage(0, 0);

    for (int kt = 0; kt < T; kt++) {
        const int s = kt & 1;
        cp_wait<0>();
        __syncthreads();
        if (kt + 1 < T) issue_stage(kt + 1, s ^ 1);

        const uint32_t aS = aBase + s * GEMM_STAGE_BYTES;
        const uint32_t bS = bBase + s * GEMM_STAGE_BYTES;
        #pragma unroll
        for (int ks = 0; ks < 4; ks++) {
            const uint32_t ko = (uint32_t)(ks << 5);
            uint32_t af[4][4];
            #pragma unroll
            for (int mt = 0; mt < 4; mt++)
                ldsm4(aS + mt * (16 * GP_BYTES) + ko, af[mt]);
            uint32_t bf0[4], bf1[4];
            ldsm4(bS + ko, bf0);
            ldsm4(bS + 16 * GP_BYTES + ko, bf1);
            #pragma unroll
            for (int mt = 0; mt < 4; mt++) {
                mma_f16(acc[mt][0], af[mt], bf0[0], bf0[1]);
                mma_f16(acc[mt][1], af[mt], bf0[2], bf0[3]);
                mma_f16(acc[mt][2], af[mt], bf1[0], bf1[1]);
                mma_f16(acc[mt][3], af[mt], bf1[2], bf1[3]);
            }
        }
        __syncthreads();
    }

    const int g   = lane >> 2;
    const int tig = lane & 3;
    if (half_out) {
        __half* Ch = (__half*)C;
        #pragma unroll
        for (int mt = 0; mt < 4; mt++) {
            int r0 = bm + warp_m * 64 + mt * 16 + g;
            #pragma unroll
            for (int nt = 0; nt < 4; nt++) {
                int c = bn + warp_n * 32 + nt * 8 + (tig << 1);
                *(uint32_t*)(Ch + (size_t)r0 * N + c)       = packh2(acc[mt][nt][0], acc[mt][nt][1]);
                *(uint32_t*)(Ch + (size_t)(r0 + 8) * N + c) = packh2(acc[mt][nt][2], acc[mt][nt][3]);
            }
        }
    } else {
        float* Cf = (float*)C;
        #pragma unroll
        for (int mt = 0; mt < 4; mt++) {
            int r0 = bm + warp_m * 64 + mt * 16 + g;
            #pragma unroll
            for (int nt = 0; nt < 4; nt++) {
                int c = bn + warp_n * 32 + nt * 8 + (tig << 1);
                *(float2*)(Cf + (size_t)r0 * N + c)       = make_float2(acc[mt][nt][0], acc[mt][nt][1]);
                *(float2*)(Cf + (size_t)(r0 + 8) * N + c) = make_float2(acc[mt][nt][2], acc[mt][nt][3]);
            }
        }
    }
}

// ---------------- fp16 NT GEMM 128x256, warp tile 64x64 (Q/O projections) --------
// 8 warps 2x4; per k16: 8 LDSM for 32 mmas -> 0.0625 B/MAC (mma-bound).
#define GB_A_STAGE (128 * GP_BYTES)          // 18432
#define GB_B_STAGE (256 * GP_BYTES)          // 36864
#define GB_SMEM_BYTES (2 * (GB_A_STAGE + GB_B_STAGE))  // 110592

__global__ void __launch_bounds__(256, 1) gemm_f16_big_kernel(
    const __half* __restrict__ A, const __half* __restrict__ Bw,
    void* __restrict__ C, int M, int N, int K, int half_out)
{
    extern __shared__ char smc[];
    const uint32_t smb = smem_u32(smc);

    const int tid    = threadIdx.x;
    const int lane   = tid & 31;
    const int wid    = tid >> 5;
    const int warp_m = wid & 1;     // 64 rows
    const int warp_n = wid >> 1;    // 64 cols
    const int bm     = blockIdx.y << 7;
    const int bn     = blockIdx.x << 8;

    const int qd   = lane >> 3;
    const int lr   = lane & 7;
    const int arow = ((qd & 1) << 3) + lr;
    const uint32_t acol = (uint32_t)((qd >> 1) << 4);
    const int brow = ((qd >> 1) << 3) + lr;
    const uint32_t bcol = (uint32_t)((qd & 1) << 4);

    const uint32_t aBase = smb + (uint32_t)(warp_m * 64 + arow) * GP_BYTES + acol;
    const uint32_t bBase = smb + 2 * GB_A_STAGE
                         + (uint32_t)(warp_n * 64 + brow) * GP_BYTES + bcol;

    float acc[4][8][4];
    #pragma unroll
    for (int mt = 0; mt < 4; mt++)
        #pragma unroll
        for (int nt = 0; nt < 8; nt++)
            #pragma unroll
            for (int r = 0; r < 4; r++) acc[mt][nt][r] = 0.0f;

    auto issue_stage = [&](int kt, int s) {
        uint32_t dA = smb + s * GB_A_STAGE;
        uint32_t dB = smb + 2 * GB_A_STAGE + s * GB_B_STAGE;
        const int koff = kt << 6;
        #pragma unroll
        for (int i = 0; i < 12; i++) {
            int idx = tid + (i << 8);        // 0..3071
            int row = idx >> 3;              // 0..383
            int ch  = idx & 7;
            if (row < 128) {
                cp16(dA + row * GP_BYTES + (ch << 4),
                     A + (size_t)(bm + row) * K + koff + (ch << 3));
            } else {
                int r2 = row - 128;
                cp16(dB + r2 * GP_BYTES + (ch << 4),
                     Bw + (size_t)(bn + r2) * K + koff + (ch << 3));
            }
        }
        cp_commit();
    };

    const int T = K >> 6;
    issue_stage(0, 0);

    for (int kt = 0; kt < T; kt++) {
        const int s = kt & 1;
        cp_wait<0>();
        __syncthreads();
        if (kt + 1 < T) issue_stage(kt + 1, s ^ 1);

        const uint32_t aS = aBase + s * GB_A_STAGE;
        const uint32_t bS = bBase + s * GB_B_STAGE;
        #pragma unroll
        for (int ks = 0; ks < 4; ks++) {
            const uint32_t ko = (uint32_t)(ks << 5);
            uint32_t af[4][4];
            #pragma unroll
            for (int mt = 0; mt < 4; mt++)
                ldsm4(aS + mt * (16 * GP_BYTES) + ko, af[mt]);
            uint32_t bf[4][4];
            #pragma unroll
            for (int j = 0; j < 4; j++)
                ldsm4(bS + j * (16 * GP_BYTES) + ko, bf[j]);
            #pragma unroll
            for (int mt = 0; mt < 4; mt++)
                #pragma unroll
                for (int j = 0; j < 4; j++) {
                    mma_f16(acc[mt][2 * j],     af[mt], bf[j][0], bf[j][1]);
                    mma_f16(acc[mt][2 * j + 1], af[mt], bf[j][2], bf[j][3]);
                }
        }
        __syncthreads();
    }

    const int g   = lane >> 2;
    const int tig = lane & 3;
    if (half_out) {
        __half* Ch = (__half*)C;
        #pragma unroll
        for (int mt = 0; mt < 4; mt++) {
            int r0 = bm + warp_m * 64 + mt * 16 + g;
            #pragma unroll
            for (int nt = 0; nt < 8; nt++) {
                int c = bn + warp_n * 64 + nt * 8 + (tig << 1);
                *(uint32_t*)(Ch + (size_t)r0 * N + c)       = packh2(acc[mt][nt][0], acc[mt][nt][1]);
                *(uint32_t*)(Ch + (size_t)(r0 + 8) * N + c) = packh2(acc[mt][nt][2], acc[mt][nt][3]);
            }
        }
    } else {
        float* Cf = (float*)C;
        #pragma unroll
        for (int mt = 0; mt < 4; mt++) {
            int r0 = bm + warp_m * 64 + mt * 16 + g;
            #pragma unroll
            for (int nt = 0; nt < 8; nt++) {
                int c = bn + warp_n * 64 + nt * 8 + (tig << 1);
                *(float2*)(Cf + (size_t)r0 * N + c)       = make_float2(acc[mt][nt][0], acc[mt][nt][1]);
                *(float2*)(Cf + (size_t)(r0 + 8) * N + c) = make_float2(acc[mt][nt][2], acc[mt][nt][3]);
            }
        }
    }
}

// ---------------- fp16 flash attention (causal), 128q x 64kv ----------------
// 256 threads, 8 warps: wm=wid&3 -> rows wm*32 (2 m16 tiles), wn=wid>>2 ->
// kv half (S) / dk half (PV). smem: Qs[128x136h]@0, KVs[64x136h]@34816,
// Ps f32[128x68]@52224, Pf[128x72h]@87040, smM/L/F@105472+.
#define ATTN_SMEM_BYTES 107008
#define QK_PITCH 272
#define PF_PITCH 144

__global__ void __launch_bounds__(256, 2) attn_kernel() {
    extern __shared__ char smc[];
    float* Ps  = (float*)(smc + 52224);
    float* smM = (float*)(smc + 105472);
    float* smL = (float*)(smc + 105984);
    float* smF = (float*)(smc + 106496);
    const uint32_t smb = smem_u32(smc);

    const int tid  = threadIdx.x;
    const int lane = tid & 31;
    const int wid  = tid >> 5;
    const int wm   = wid & 3;
    const int wn   = wid >> 2;
    const int m_   = lane & 3;
    const int rr   = lane >> 2;

    const int qb  = blockIdx.x;
    const int h   = blockIdx.y;
    const int b   = blockIdx.z;
    const int q0  = qb << 7;
    const int kvh = h >> 2;

    const __half* Qg = g_Q + (size_t)(b * L_ + q0) * D_ + h * DK_;
    const __half* Kg = g_K + (size_t)(b * L_) * DKV_ + kvh * DK_;
    const __half* Vg = g_V + (size_t)(b * L_) * DKV_ + kvh * DK_;

    const int qd = lane >> 3;
    const int lr = lane & 7;
    const int arow = ((qd & 1) << 3) + lr;
    const uint32_t acol = (uint32_t)((qd >> 1) << 4);
    const int brow = ((qd >> 1) << 3) + lr;
    const uint32_t bcol = (uint32_t)((qd & 1) << 4);

    const uint32_t aQ0 = smb + (uint32_t)(wm * 32 + arow) * QK_PITCH + acol;
    const uint32_t bK  = smb + 34816 + (uint32_t)(wn * 32 + brow) * QK_PITCH + bcol;
    const uint32_t aP0 = smb + 87040 + (uint32_t)(wm * 32 + arow) * PF_PITCH + acol;
    const uint32_t vB  = smb + 34816 + (uint32_t)(((qd & 1) << 3) + lr) * QK_PITCH
                       + (uint32_t)(wn * 64 + ((qd >> 1) << 3)) * 2;

    // ---- stage Q (128 rows) ----
    #pragma unroll
    for (int i = 0; i < 8; i++) {
        int idx = tid + (i << 8);            // 0..2047
        int row = idx >> 4;
        int ch  = idx & 15;
        uint4 v = *(const uint4*)(Qg + (size_t)row * D_ + (ch << 3));
        *(uint4*)(smc + row * QK_PITCH + (ch << 4)) = v;
    }
    if (tid < 128) { smM[tid] = -1e30f; smL[tid] = 0.0f; }

    float o[2][8][4];
    #pragma unroll
    for (int mt = 0; mt < 2; mt++)
        #pragma unroll
        for (int j = 0; j < 8; j++)
            #pragma unroll
            for (int r = 0; r < 4; r++) o[mt][j][r] = 0.0f;

    const float scale = 0.08838834764831845f;
    const int nkb = 2 * qb + 2;

    for (int kb = 0; kb < nkb; kb++) {
        const int k0 = kb << 6;
        __syncthreads();   // prev PV reads of KVs/Pf done; Q ready (iter 0)

        // ---- stage K (64 rows) ----
        #pragma unroll
        for (int i = 0; i < 4; i++) {
            int idx = tid + (i << 8);
            int row = idx >> 4;
            int ch  = idx & 15;
            uint4 v = *(const uint4*)(Kg + (size_t)(k0 + row) * DKV_ + (ch << 3));
            *(uint4*)(smc + 34816 + row * QK_PITCH + (ch << 4)) = v;
        }
        __syncthreads();

        // ---- S = Q K^T ----
        {
            float s4[2][4][4];
            #pragma unroll
            for (int mt = 0; mt < 2; mt++)
                #pragma unroll
                for (int j = 0; j < 4; j++)
                    #pragma unroll
                    for (int r = 0; r < 4; r++) s4[mt][j][r] = 0.0f;

            #pragma unroll
            for (int ks = 0; ks < 8; ks++) {
                const uint32_t ko = (uint32_t)(ks << 5);
                uint32_t af[2][4], bf0[4], bf1[4];
                ldsm4(aQ0 + ko, af[0]);
                ldsm4(aQ0 + 16 * QK_PITCH + ko, af[1]);
                ldsm4(bK + ko, bf0);
                ldsm4(bK + 16 * QK_PITCH + ko, bf1);
                #pragma unroll
                for (int mt = 0; mt < 2; mt++) {
                    mma_f16(s4[mt][0], af[mt], bf0[0], bf0[1]);
                    mma_f16(s4[mt][1], af[mt], bf0[2], bf0[3]);
                    mma_f16(s4[mt][2], af[mt], bf1[0], bf1[1]);
                    mma_f16(s4[mt][3], af[mt], bf1[2], bf1[3]);
                }
            }

            #pragma unroll
            for (int mt = 0; mt < 2; mt++) {
                int r0 = wm * 32 + mt * 16 + rr;
                int r1 = r0 + 8;
                #pragma unroll
                for (int j = 0; j < 4; j++) {
                    int c0 = wn * 32 + j * 8 + (m_ << 1);
                    float v00 = s4[mt][j][0] * scale, v01 = s4[mt][j][1] * scale;
                    float v10 = s4[mt][j][2] * scale, v11 = s4[mt][j][3] * scale;
                    if (k0 + c0     > q0 + r0) v00 = -1e30f;
                    if (k0 + c0 + 1 > q0 + r0) v01 = -1e30f;
                    if (k0 + c0     > q0 + r1) v10 = -1e30f;
                    if (k0 + c0 + 1 > q0 + r1) v11 = -1e30f;
                    *(float2*)&Ps[r0 * 68 + c0] = make_float2(v00, v01);
                    *(float2*)&Ps[r1 * 68 + c0] = make_float2(v10, v11);
                }
            }
        }
        __syncthreads();   // Ps ready; K reads done -> KVs reusable for V

        // ---- stage V (64 rows, overwrites K) ----
        #pragma unroll
        for (int i = 0; i < 4; i++) {
            int idx = tid + (i << 8);
            int row = idx >> 4;
            int ch  = idx & 15;
            uint4 v = *(const uint4*)(Vg + (size_t)(k0 + row) * DKV_ + (ch << 3));
            *(uint4*)(smc + 34816 + row * QK_PITCH + (ch << 4)) = v;
        }

        // ---- online softmax: 2 threads per row; exp -> Pf (fp16) ----
        {
            int r   = tid >> 1;
            int seg = tid & 1;
            float v[32];
            #pragma unroll
            for (int q = 0; q < 8; q++) {
                float4 t = *(float4*)&Ps[r * 68 + seg * 32 + (q << 2)];
                v[q * 4 + 0] = t.x; v[q * 4 + 1] = t.y;
                v[q * 4 + 2] = t.z; v[q * 4 + 3] = t.w;
            }
            float mx = v[0];
            #pragma unroll
            for (int q = 1; q < 32; q++) mx = fmaxf(mx, v[q]);
            mx = fmaxf(mx, __shfl_xor_sync(0xffffffffu, mx, 1));
            float m_old = smM[r];
            float m_new = fmaxf(m_old, mx);
            float sum = 0.0f;
            #pragma unroll
            for (int q = 0; q < 32; q++) {
                v[q] = __expf(v[q] - m_new);
                sum += v[q];
            }
            sum += __shfl_xor_sync(0xffffffffu, sum, 1);
            float fac = __expf(m_old - m_new);
            if (seg == 0) {
                smM[r] = m_new;
                smL[r] = smL[r] * fac + sum;
                smF[r] = fac;
            }
            char* pd = smc + 87040 + r * PF_PITCH + seg * 64;
            #pragma unroll
            for (int q = 0; q < 4; q++) {
                uint4 w;
                w.x = packh2(v[q * 8 + 0], v[q * 8 + 1]);
                w.y = packh2(v[q * 8 + 2], v[q * 8 + 3]);
                w.z = packh2(v[q * 8 + 4], v[q * 8 + 5]);
                w.w = packh2(v[q * 8 + 6], v[q * 8 + 7]);
                *(uint4*)(pd + (q << 4)) = w;
            }
        }
        __syncthreads();   // V + Pf + smF ready

        // ---- rescale O, then O += P V (V via ldmatrix.trans) ----
        {
            float f[2][2];
            #pragma unroll
            for (int mt = 0; mt < 2; mt++) {
                int r0 = wm * 32 + mt * 16 + rr;
                f[mt][0] = smF[r0];
                f[mt][1] = smF[r0 + 8];
            }
            #pragma unroll
            for (int mt = 0; mt < 2; mt++)
                #pragma unroll
                for (int j = 0; j < 8; j++) {
                    o[mt][j][0] *= f[mt][0]; o[mt][j][1] *= f[mt][0];
                    o[mt][j][2] *= f[mt][1]; o[mt][j][3] *= f[mt][1];
                }
            #pragma unroll
            for (int ks = 0; ks < 4; ks++) {
                uint32_t pf[2][4];
                ldsm4(aP0 + (uint32_t)(ks << 5), pf[0]);
                ldsm4(aP0 + 16 * PF_PITCH + (uint32_t)(ks << 5), pf[1]);
                const uint32_t vk = vB + (uint32_t)(ks * 16 * QK_PITCH);
                #pragma unroll
                for (int t = 0; t < 4; t++) {
                    uint32_t vf[4];
                    ldsm4t(vk + (uint32_t)(t << 5), vf);
                    #pragma unroll
                    for (int mt = 0; mt < 2; mt++) {
                        mma_f16(o[mt][2 * t],     pf[mt], vf[0], vf[1]);
                        mma_f16(o[mt][2 * t + 1], pf[mt], vf[2], vf[3]);
                    }
                }
            }
        }
    }

    // ---- epilogue: normalize, write g_O (fp16) ----
    #pragma unroll
    for (int mt = 0; mt < 2; mt++) {
        int r0 = wm * 32 + mt * 16 + rr;
        int r1 = r0 + 8;
        float inv0 = 1.0f / smL[r0];
        float inv1 = 1.0f / smL[r1];
        __half* op0 = g_O + (size_t)(b * L_ + q0 + r0) * D_ + h * DK_;
        __half* op1 = g_O + (size_t)(b * L_ + q0 + r1) * D_ + h * DK_;
        #pragma unroll
        for (int j = 0; j < 8; j++) {
            int n = wn * 64 + j * 8 + (m_ << 1);
            *(uint32_t*)(op0 + n) = packh2(o[mt][j][0] * inv0, o[mt][j][1] * inv0);
            *(uint32_t*)(op1 + n) = packh2(o[mt][j][2] * inv1, o[mt][j][3] * inv1);
        }
    }
}

// ---------------- launch ----------------
extern "C" void kernel_launch(void* const* d_in, const int* in_sizes, int n_in,
                              void* d_out, int out_size) {
    const float* query = (const float*)d_in[0];
    const float* key_t = (const float*)d_in[1];
    const float* value = (const float*)d_in[2];
    // d_in[3] = mask (causal tril; unused)
    const float* Wq = (const float*)d_in[4];
    const float* Wk = (const float*)d_in[5];
    const float* Wv = (const float*)d_in[6];
    const float* Wo = (const float*)d_in[7];
    float* out = (float*)d_out;

    __half *Xq, *Xk, *Xv, *Whq, *Whk, *Whv, *Who, *Qb, *Kb, *Vb, *Ob;
    cudaGetSymbolAddress((void**)&Xq,  g_Xq);
    cudaGetSymbolAddress((void**)&Xk,  g_Xk);
    cudaGetSymbolAddress((void**)&Xv,  g_Xv);
    cudaGetSymbolAddress((void**)&Whq, g_Wq);
    cudaGetSymbolAddress((void**)&Whk, g_Wk);
    cudaGetSymbolAddress((void**)&Whv, g_Wv);
    cudaGetSymbolAddress((void**)&Who, g_Wo);
    cudaGetSymbolAddress((void**)&Qb,  g_Q);
    cudaGetSymbolAddress((void**)&Kb,  g_K);
    cudaGetSymbolAddress((void**)&Vb,  g_V);
    cudaGetSymbolAddress((void**)&Ob,  g_O);

    cudaFuncSetAttribute(gemm_f16_kernel, cudaFuncAttributeMaxDynamicSharedMemorySize,
                         GEMM_SMEM_BYTES);
    cudaFuncSetAttribute(gemm_f16_big_kernel, cudaFuncAttributeMaxDynamicSharedMemorySize,
                         GB_SMEM_BYTES);
    cudaFuncSetAttribute(attn_kernel, cudaFuncAttributeMaxDynamicSharedMemorySize,
                         ATTN_SMEM_BYTES);

    rope_table_kernel<<<512, 256>>>();

    const int n4_big = (M_ * D_) / 4;
    const int n4_w   = (D_ * D_) / 4;
    const int n4_kv  = (DKV_ * D_) / 4;
    f32_to_f16_kernel<<<n4_big / 256, 256>>>(query, Xq, n4_big);
    f32_to_f16_kernel<<<n4_big / 256, 256>>>(key_t, Xk, n4_big);
    f32_to_f16_kernel<<<n4_big / 256, 256>>>(value, Xv, n4_big);
    f32_to_f16_kernel<<<n4_w / 256, 256>>>(Wq, Whq, n4_w);
    f32_to_f16_kernel<<<n4_kv / 256, 256>>>(Wk, Whk, n4_kv);
    f32_to_f16_kernel<<<n4_kv / 256, 256>>>(Wv, Whv, n4_kv);
    f32_to_f16_kernel<<<n4_w / 256, 256>>>(Wo, Who, n4_w);

    // Projections
    gemm_f16_big_kernel<<<dim3(D_ / 256, M_ / 128), 256, GB_SMEM_BYTES>>>(
        Xq, Whq, Qb, M_, D_, D_, 1);
    gemm_f16_kernel<<<dim3(DKV_ / 128, M_ / 128), 256, GEMM_SMEM_BYTES>>>(
        Xk, Whk, Kb, M_, DKV_, D_, 1);
    gemm_f16_kernel<<<dim3(DKV_ / 128, M_ / 128), 256, GEMM_SMEM_BYTES>>>(
        Xv, Whv, Vb, M_, DKV_, D_, 1);

    // RoPE + clip
    rope_apply_kernel<<<(M_ * H_ * 64) / 256, 256>>>(Qb, H_, D_);
    rope_apply_kernel<<<(M_ * KVH_ * 64) / 256, 256>>>(Kb, KVH_, DKV_);

    // Attention (128q x 64kv tiles)
    attn_kernel<<<dim3(L_ / 128, H_, B_), 256, ATTN_SMEM_BYTES>>>();

    // Output projection (fp32 out)
    gemm_f16_big_kernel<<<dim3(D_ / 256, M_ / 128), 256, GB_SMEM_BYTES>>>(
        Ob, Who, out, M_, D_, D_, 0);
}

// round 15
// speedup vs baseline: 2.3296x; 1.1204x over previous
#include <cuda_runtime.h>
#include <cuda_fp16.h>
#include <math.h>
#include <stdint.h>

// Problem constants
#define B_    2
#define L_    2048
#define D_    2048
#define H_    16
#define KVH_  4
#define DK_   128
#define DKV_  512            // KVH_ * DK_
#define M_    (B_ * L_)      // 4096 rows
#define CAPV  50.0f

// ---------------- scratch (static device globals; no allocation) ----------------
static __device__ __half g_Xq[(size_t)M_ * D_];
static __device__ __half g_Xk[(size_t)M_ * D_];
static __device__ __half g_Xv[(size_t)M_ * D_];
static __device__ __half g_Wq[(size_t)D_ * D_];
static __device__ __half g_Wk[(size_t)DKV_ * D_];
static __device__ __half g_Wv[(size_t)DKV_ * D_];
static __device__ __half g_Wo[(size_t)D_ * D_];
static __device__ __half g_Q[(size_t)M_ * D_];
static __device__ __half g_K[(size_t)M_ * DKV_];
static __device__ __half g_V[(size_t)M_ * DKV_];
static __device__ __half g_O[(size_t)M_ * D_];
static __device__ float  g_cos[L_ * 64];
static __device__ float  g_sin[L_ * 64];

// ---------------- fp32 -> fp16 convert ----------------
__global__ void f32_to_f16_kernel(const float* __restrict__ src,
                                  __half* __restrict__ dst, int n4) {
    int i = blockIdx.x * blockDim.x + threadIdx.x;
    if (i >= n4) return;
    float4 v = ((const float4*)src)[i];
    __half2 a = __floats2half2_rn(v.x, v.y);
    __half2 b = __floats2half2_rn(v.z, v.w);
    uint2 u;
    u.x = *(uint32_t*)&a;
    u.y = *(uint32_t*)&b;
    ((uint2*)dst)[i] = u;
}

// ---------------- RoPE table ----------------
__global__ void rope_table_kernel() {
    int idx = blockIdx.x * blockDim.x + threadIdx.x;
    if (idx >= L_ * 64) return;
    int pos = idx >> 6;
    int i   = idx & 63;
    float expnt = (float)(2 * i) / 128.0f;
    float invf  = powf(10000.0f, -expnt);
    float f     = (float)pos * invf;
    g_cos[idx] = cosf(f);
    g_sin[idx] = sinf(f);
}

// ---------------- RoPE apply + clip (in place, fp16) ----------------
__global__ void rope_apply_kernel(__half* __restrict__ X, int heads, int rowstride) {
    int idx   = blockIdx.x * blockDim.x + threadIdx.x;
    int total = M_ * heads * 64;
    if (idx >= total) return;
    int i   = idx & 63;
    int t   = idx >> 6;
    int h   = t % heads;
    int row = t / heads;
    int pos = row & (L_ - 1);
    float c = g_cos[(pos << 6) + i];
    float s = g_sin[(pos << 6) + i];
    __half* p = X + (size_t)row * rowstride + h * DK_ + i;
    float x1 = __half2float(p[0]), x2 = __half2float(p[64]);
    float o1 = x1 * c - x2 * s;
    float o2 = x1 * s + x2 * c;
    p[0]  = __float2half_rn(fminf(fmaxf(o1, -CAPV), CAPV));
    p[64] = __float2half_rn(fminf(fmaxf(o2, -CAPV), CAPV));
}

// ---------------- mma / ldmatrix / cp.async helpers ----------------
__device__ __forceinline__ uint32_t smem_u32(const void* p) {
    return (uint32_t)__cvta_generic_to_shared(p);
}
__device__ __forceinline__ void ldsm4(uint32_t addr, uint32_t* r) {
    asm volatile("ldmatrix.sync.aligned.m8n8.x4.shared.b16 {%0,%1,%2,%3}, [%4];"
        : "=r"(r[0]), "=r"(r[1]), "=r"(r[2]), "=r"(r[3]) : "r"(addr));
}
__device__ __forceinline__ void ldsm4t(uint32_t addr, uint32_t* r) {
    asm volatile("ldmatrix.sync.aligned.m8n8.x4.trans.shared.b16 {%0,%1,%2,%3}, [%4];"
        : "=r"(r[0]), "=r"(r[1]), "=r"(r[2]), "=r"(r[3]) : "r"(addr));
}
__device__ __forceinline__ void mma_f16(float* c, const uint32_t* a,
                                        uint32_t b0, uint32_t b1) {
    asm volatile(
        "mma.sync.aligned.m16n8k16.row.col.f32.f16.f16.f32 "
        "{%0,%1,%2,%3}, {%4,%5,%6,%7}, {%8,%9}, {%0,%1,%2,%3};"
        : "+f"(c[0]), "+f"(c[1]), "+f"(c[2]), "+f"(c[3])
        : "r"(a[0]), "r"(a[1]), "r"(a[2]), "r"(a[3]), "r"(b0), "r"(b1));
}
__device__ __forceinline__ void cp16(uint32_t smem_dst, const void* gsrc) {
    asm volatile("cp.async.ca.shared.global [%0], [%1], 16;" :: "r"(smem_dst), "l"(gsrc));
}
__device__ __forceinline__ void cp_commit() {
    asm volatile("cp.async.commit_group;");
}
template <int N>
__device__ __forceinline__ void cp_wait() {
    asm volatile("cp.async.wait_group %0;" :: "n"(N));
}
__device__ __forceinline__ uint32_t packh2(float a, float b) {
    __half2 h = __floats2half2_rn(a, b);
    return *(uint32_t*)&h;
}

#define GP_BYTES 144   // smem pitch: 64 fp16 data + pad (36 words, 4 mod 32)

// ---------------- fp16 NT GEMM 128x128 (KV projections) ----------------
#define GEMM_STAGE_BYTES (128 * GP_BYTES)
#define GEMM_SMEM_BYTES  (2 * 2 * GEMM_STAGE_BYTES)  // 73728

__global__ void __launch_bounds__(256, 2) gemm_f16_kernel(
    const __half* __restrict__ A, const __half* __restrict__ Bw,
    void* __restrict__ C, int M, int N, int K, int half_out)
{
    extern __shared__ char smc[];
    const uint32_t smb = smem_u32(smc);

    const int tid    = threadIdx.x;
    const int lane   = tid & 31;
    const int wid    = tid >> 5;
    const int warp_m = wid & 1;
    const int warp_n = wid >> 1;
    const int bm     = blockIdx.y << 7;
    const int bn     = blockIdx.x << 7;

    const int qd   = lane >> 3;
    const int lr   = lane & 7;
    const int arow = ((qd & 1) << 3) + lr;
    const uint32_t acol = (uint32_t)((qd >> 1) << 4);
    const int brow = ((qd >> 1) << 3) + lr;
    const uint32_t bcol = (uint32_t)((qd & 1) << 4);

    const uint32_t aBase = smb + (uint32_t)(warp_m * 64 + arow) * GP_BYTES + acol;
    const uint32_t bBase = smb + 2 * GEMM_STAGE_BYTES
                         + (uint32_t)(warp_n * 32 + brow) * GP_BYTES + bcol;

    float acc[4][4][4];
    #pragma unroll
    for (int mt = 0; mt < 4; mt++)
        #pragma unroll
        for (int nt = 0; nt < 4; nt++)
            #pragma unroll
            for (int r = 0; r < 4; r++) acc[mt][nt][r] = 0.0f;

    auto issue_stage = [&](int kt, int s) {
        uint32_t dA = smb + s * GEMM_STAGE_BYTES;
        uint32_t dB = smb + (2 + s) * GEMM_STAGE_BYTES;
        const int koff = kt << 6;
        #pragma unroll
        for (int i = 0; i < 4; i++) {
            int idx = tid + (i << 8);
            int row = idx >> 3;
            int ch  = idx & 7;
            cp16(dA + row * GP_BYTES + (ch << 4),
                 A  + (size_t)(bm + row) * K + koff + (ch << 3));
            cp16(dB + row * GP_BYTES + (ch << 4),
                 Bw + (size_t)(bn + row) * K + koff + (ch << 3));
        }
        cp_commit();
    };

    const int T = K >> 6;
    issue_stage(0, 0);

    for (int kt = 0; kt < T; kt++) {
        const int s = kt & 1;
        cp_wait<0>();
        __syncthreads();
        if (kt + 1 < T) issue_stage(kt + 1, s ^ 1);

        const uint32_t aS = aBase + s * GEMM_STAGE_BYTES;
        const uint32_t bS = bBase + s * GEMM_STAGE_BYTES;
        #pragma unroll
        for (int ks = 0; ks < 4; ks++) {
            const uint32_t ko = (uint32_t)(ks << 5);
            uint32_t af[4][4];
            #pragma unroll
            for (int mt = 0; mt < 4; mt++)
                ldsm4(aS + mt * (16 * GP_BYTES) + ko, af[mt]);
            uint32_t bf0[4], bf1[4];
            ldsm4(bS + ko, bf0);
            ldsm4(bS + 16 * GP_BYTES + ko, bf1);
            #pragma unroll
            for (int mt = 0; mt < 4; mt++) {
                mma_f16(acc[mt][0], af[mt], bf0[0], bf0[1]);
                mma_f16(acc[mt][1], af[mt], bf0[2], bf0[3]);
                mma_f16(acc[mt][2], af[mt], bf1[0], bf1[1]);
                mma_f16(acc[mt][3], af[mt], bf1[2], bf1[3]);
            }
        }
        __syncthreads();
    }

    const int g   = lane >> 2;
    const int tig = lane & 3;
    if (half_out) {
        __half* Ch = (__half*)C;
        #pragma unroll
        for (int mt = 0; mt < 4; mt++) {
            int r0 = bm + warp_m * 64 + mt * 16 + g;
            #pragma unroll
            for (int nt = 0; nt < 4; nt++) {
                int c = bn + warp_n * 32 + nt * 8 + (tig << 1);
                *(uint32_t*)(Ch + (size_t)r0 * N + c)       = packh2(acc[mt][nt][0], acc[mt][nt][1]);
                *(uint32_t*)(Ch + (size_t)(r0 + 8) * N + c) = packh2(acc[mt][nt][2], acc[mt][nt][3]);
            }
        }
    } else {
        float* Cf = (float*)C;
        #pragma unroll
        for (int mt = 0; mt < 4; mt++) {
            int r0 = bm + warp_m * 64 + mt * 16 + g;
            #pragma unroll
            for (int nt = 0; nt < 4; nt++) {
                int c = bn + warp_n * 32 + nt * 8 + (tig << 1);
                *(float2*)(Cf + (size_t)r0 * N + c)       = make_float2(acc[mt][nt][0], acc[mt][nt][1]);
                *(float2*)(Cf + (size_t)(r0 + 8) * N + c) = make_float2(acc[mt][nt][2], acc[mt][nt][3]);
            }
        }
    }
}

// ---------------- fp16 NT GEMM 128x256, warp tile 64x64 (Q/O projections) --------
#define GB_A_STAGE (128 * GP_BYTES)          // 18432
#define GB_B_STAGE (256 * GP_BYTES)          // 36864
#define GB_SMEM_BYTES (2 * (GB_A_STAGE + GB_B_STAGE))  // 110592

__global__ void __launch_bounds__(256, 1) gemm_f16_big_kernel(
    const __half* __restrict__ A, const __half* __restrict__ Bw,
    void* __restrict__ C, int M, int N, int K, int half_out)
{
    extern __shared__ char smc[];
    const uint32_t smb = smem_u32(smc);

    const int tid    = threadIdx.x;
    const int lane   = tid & 31;
    const int wid    = tid >> 5;
    const int warp_m = wid & 1;
    const int warp_n = wid >> 1;
    const int bm     = blockIdx.y << 7;
    const int bn     = blockIdx.x << 8;

    const int qd   = lane >> 3;
    const int lr   = lane & 7;
    const int arow = ((qd & 1) << 3) + lr;
    const uint32_t acol = (uint32_t)((qd >> 1) << 4);
    const int brow = ((qd >> 1) << 3) + lr;
    const uint32_t bcol = (uint32_t)((qd & 1) << 4);

    const uint32_t aBase = smb + (uint32_t)(warp_m * 64 + arow) * GP_BYTES + acol;
    const uint32_t bBase = smb + 2 * GB_A_STAGE
                         + (uint32_t)(warp_n * 64 + brow) * GP_BYTES + bcol;

    float acc[4][8][4];
    #pragma unroll
    for (int mt = 0; mt < 4; mt++)
        #pragma unroll
        for (int nt = 0; nt < 8; nt++)
            #pragma unroll
            for (int r = 0; r < 4; r++) acc[mt][nt][r] = 0.0f;

    auto issue_stage = [&](int kt, int s) {
        uint32_t dA = smb + s * GB_A_STAGE;
        uint32_t dB = smb + 2 * GB_A_STAGE + s * GB_B_STAGE;
        const int koff = kt << 6;
        #pragma unroll
        for (int i = 0; i < 12; i++) {
            int idx = tid + (i << 8);
            int row = idx >> 3;
            int ch  = idx & 7;
            if (row < 128) {
                cp16(dA + row * GP_BYTES + (ch << 4),
                     A + (size_t)(bm + row) * K + koff + (ch << 3));
            } else {
                int r2 = row - 128;
                cp16(dB + r2 * GP_BYTES + (ch << 4),
                     Bw + (size_t)(bn + r2) * K + koff + (ch << 3));
            }
        }
        cp_commit();
    };

    const int T = K >> 6;
    issue_stage(0, 0);

    for (int kt = 0; kt < T; kt++) {
        const int s = kt & 1;
        cp_wait<0>();
        __syncthreads();
        if (kt + 1 < T) issue_stage(kt + 1, s ^ 1);

        const uint32_t aS = aBase + s * GB_A_STAGE;
        const uint32_t bS = bBase + s * GB_B_STAGE;
        #pragma unroll
        for (int ks = 0; ks < 4; ks++) {
            const uint32_t ko = (uint32_t)(ks << 5);
            uint32_t af[4][4];
            #pragma unroll
            for (int mt = 0; mt < 4; mt++)
                ldsm4(aS + mt * (16 * GP_BYTES) + ko, af[mt]);
            uint32_t bf[4][4];
            #pragma unroll
            for (int j = 0; j < 4; j++)
                ldsm4(bS + j * (16 * GP_BYTES) + ko, bf[j]);
            #pragma unroll
            for (int mt = 0; mt < 4; mt++)
                #pragma unroll
                for (int j = 0; j < 4; j++) {
                    mma_f16(acc[mt][2 * j],     af[mt], bf[j][0], bf[j][1]);
                    mma_f16(acc[mt][2 * j + 1], af[mt], bf[j][2], bf[j][3]);
                }
        }
        __syncthreads();
    }

    const int g   = lane >> 2;
    const int tig = lane & 3;
    if (half_out) {
        __half* Ch = (__half*)C;
        #pragma unroll
        for (int mt = 0; mt < 4; mt++) {
            int r0 = bm + warp_m * 64 + mt * 16 + g;
            #pragma unroll
            for (int nt = 0; nt < 8; nt++) {
                int c = bn + warp_n * 64 + nt * 8 + (tig << 1);
                *(uint32_t*)(Ch + (size_t)r0 * N + c)       = packh2(acc[mt][nt][0], acc[mt][nt][1]);
                *(uint32_t*)(Ch + (size_t)(r0 + 8) * N + c) = packh2(acc[mt][nt][2], acc[mt][nt][3]);
            }
        }
    } else {
        float* Cf = (float*)C;
        #pragma unroll
        for (int mt = 0; mt < 4; mt++) {
            int r0 = bm + warp_m * 64 + mt * 16 + g;
            #pragma unroll
            for (int nt = 0; nt < 8; nt++) {
                int c = bn + warp_n * 64 + nt * 8 + (tig << 1);
                *(float2*)(Cf + (size_t)r0 * N + c)       = make_float2(acc[mt][nt][0], acc[mt][nt][1]);
                *(float2*)(Cf + (size_t)(r0 + 8) * N + c) = make_float2(acc[mt][nt][2], acc[mt][nt][3]);
            }
        }
    }
}

// ---------------- fp16 flash attention (causal), FA2 register softmax -------------
// CTA: 64q x 64kv, 128 threads, 4 warps. Warp w owns q rows [16w, 16w+16) and ALL
// 64 kv / ALL 128 dk columns. Softmax entirely in regs + quad shfl (no P smem).
// S accum frags are reused directly as PV A-frags (pack c0..c3 -> fp16 pairs).
// smem: Qs 64x136h @0, Ks 64x136h @17408, Vs 64x136h @34816. Total 52224.
#define ATTN_SMEM_BYTES 52224
#define QK_PITCH 272

__global__ void __launch_bounds__(128) attn_kernel() {
    extern __shared__ char smc[];
    const uint32_t smb = smem_u32(smc);

    const int tid  = threadIdx.x;
    const int lane = tid & 31;
    const int wid  = tid >> 5;        // warp owns rows wid*16..+15
    const int m_   = lane & 3;
    const int rr   = lane >> 2;

    const int qb  = blockIdx.x;
    const int h   = blockIdx.y;
    const int b   = blockIdx.z;
    const int q0  = qb << 6;
    const int kvh = h >> 2;

    const __half* Qg = g_Q + (size_t)(b * L_ + q0) * D_ + h * DK_;
    const __half* Kg = g_K + (size_t)(b * L_) * DKV_ + kvh * DK_;
    const __half* Vg = g_V + (size_t)(b * L_) * DKV_ + kvh * DK_;

    // ldmatrix lane coords
    const int qd = lane >> 3;
    const int lr = lane & 7;
    const int arow = ((qd & 1) << 3) + lr;
    const uint32_t acol = (uint32_t)((qd >> 1) << 4);
    const int brow = ((qd >> 1) << 3) + lr;
    const uint32_t bcol = (uint32_t)((qd & 1) << 4);

    const uint32_t aQ = smb + (uint32_t)(wid * 16 + arow) * QK_PITCH + acol;
    const uint32_t bK = smb + 17408 + (uint32_t)brow * QK_PITCH + bcol;
    // V (trans-LDSM): q0/q1 quads = kv rows 0-7/8-15; q2/q3 = dk col +8
    const uint32_t vB = smb + 34816 + (uint32_t)(((qd & 1) << 3) + lr) * QK_PITCH
                      + (uint32_t)(((qd >> 1) << 3)) * 2;

    // ---- stage Q (64 rows x 128h): 128 thr x 8 uint4 ----
    #pragma unroll
    for (int i = 0; i < 8; i++) {
        int idx = tid + (i << 7);            // 0..1023
        int row = idx >> 4;
        int ch  = idx & 15;
        uint4 v = *(const uint4*)(Qg + (size_t)row * D_ + (ch << 3));
        *(uint4*)(smc + row * QK_PITCH + (ch << 4)) = v;
    }

    float o[16][4];
    #pragma unroll
    for (int j = 0; j < 16; j++)
        #pragma unroll
        for (int r = 0; r < 4; r++) o[j][r] = 0.0f;

    float m0 = -1e30f, l0 = 0.0f;    // row r0 = wid*16 + rr
    float m1 = -1e30f, l1 = 0.0f;    // row r1 = r0 + 8

    const float scale = 0.08838834764831845f;  // 1/sqrt(128)
    const int nkb = qb + 1;
    const int gr0 = q0 + wid * 16 + rr;
    const int gr1 = gr0 + 8;

    for (int kb = 0; kb < nkb; kb++) {
        const int k0 = kb << 6;
        __syncthreads();   // prev iter's PV reads of Ks/Vs done

        // ---- stage K and V (64 rows each) ----
        #pragma unroll
        for (int i = 0; i < 8; i++) {
            int idx = tid + (i << 7);
            int row = idx >> 4;
            int ch  = idx & 15;
            uint4 kv4 = *(const uint4*)(Kg + (size_t)(k0 + row) * DKV_ + (ch << 3));
            *(uint4*)(smc + 17408 + row * QK_PITCH + (ch << 4)) = kv4;
            uint4 vv4 = *(const uint4*)(Vg + (size_t)(k0 + row) * DKV_ + (ch << 3));
            *(uint4*)(smc + 34816 + row * QK_PITCH + (ch << 4)) = vv4;
        }
        __syncthreads();

        // ---- S = Q K^T : 8 n8-tiles over kv, accum f32 ----
        float s[8][4];
        #pragma unroll
        for (int j = 0; j < 8; j++)
            #pragma unroll
            for (int r = 0; r < 4; r++) s[j][r] = 0.0f;

        #pragma unroll
        for (int ks = 0; ks < 8; ks++) {
            const uint32_t ko = (uint32_t)(ks << 5);
            uint32_t af[4];
            ldsm4(aQ + ko, af);
            #pragma unroll
            for (int j = 0; j < 4; j++) {
                uint32_t bf[4];
                ldsm4(bK + j * (16 * QK_PITCH) + ko, bf);
                mma_f16(s[2 * j],     af, bf[0], bf[1]);
                mma_f16(s[2 * j + 1], af, bf[2], bf[3]);
            }
        }

        // ---- scale + causal mask (regs) ----
        #pragma unroll
        for (int j = 0; j < 8; j++) {
            int c0 = k0 + j * 8 + (m_ << 1);
            s[j][0] = (c0     <= gr0) ? s[j][0] * scale : -1e30f;
            s[j][1] = (c0 + 1 <= gr0) ? s[j][1] * scale : -1e30f;
            s[j][2] = (c0     <= gr1) ? s[j][2] * scale : -1e30f;
            s[j][3] = (c0 + 1 <= gr1) ? s[j][3] * scale : -1e30f;
        }

        // ---- register softmax (quad shfl over m_) ----
        float mx0 = s[0][0], mx1 = s[0][2];
        #pragma unroll
        for (int j = 0; j < 8; j++) {
            mx0 = fmaxf(mx0, fmaxf(s[j][0], s[j][1]));
            mx1 = fmaxf(mx1, fmaxf(s[j][2], s[j][3]));
        }
        mx0 = fmaxf(mx0, __shfl_xor_sync(0xffffffffu, mx0, 1));
        mx0 = fmaxf(mx0, __shfl_xor_sync(0xffffffffu, mx0, 2));
        mx1 = fmaxf(mx1, __shfl_xor_sync(0xffffffffu, mx1, 1));
        mx1 = fmaxf(mx1, __shfl_xor_sync(0xffffffffu, mx1, 2));
        float mn0 = fmaxf(m0, mx0);
        float mn1 = fmaxf(m1, mx1);
        float sum0 = 0.0f, sum1 = 0.0f;
        #pragma unroll
        for (int j = 0; j < 8; j++) {
            s[j][0] = __expf(s[j][0] - mn0);
            s[j][1] = __expf(s[j][1] - mn0);
            s[j][2] = __expf(s[j][2] - mn1);
            s[j][3] = __expf(s[j][3] - mn1);
            sum0 += s[j][0] + s[j][1];
            sum1 += s[j][2] + s[j][3];
        }
        sum0 += __shfl_xor_sync(0xffffffffu, sum0, 1);
        sum0 += __shfl_xor_sync(0xffffffffu, sum0, 2);
        sum1 += __shfl_xor_sync(0xffffffffu, sum1, 1);
        sum1 += __shfl_xor_sync(0xffffffffu, sum1, 2);
        float f0 = __expf(m0 - mn0);
        float f1 = __expf(m1 - mn1);
        m0 = mn0; l0 = l0 * f0 + sum0;
        m1 = mn1; l1 = l1 * f1 + sum1;

        // ---- rescale O; pack P into A-frags (regs only) ----
        #pragma unroll
        for (int j = 0; j < 16; j++) {
            o[j][0] *= f0; o[j][1] *= f0;
            o[j][2] *= f1; o[j][3] *= f1;
        }
        uint32_t pf[4][4];
        #pragma unroll
        for (int k2 = 0; k2 < 4; k2++) {
            pf[k2][0] = packh2(s[2 * k2][0],     s[2 * k2][1]);       // r0, k..k+1
            pf[k2][1] = packh2(s[2 * k2][2],     s[2 * k2][3]);       // r1
            pf[k2][2] = packh2(s[2 * k2 + 1][0], s[2 * k2 + 1][1]);   // r0, k+8..9
            pf[k2][3] = packh2(s[2 * k2 + 1][2], s[2 * k2 + 1][3]);   // r1
        }

        // ---- O += P V (V frags via ldmatrix.trans; 16 dk n-tiles) ----
        #pragma unroll
        for (int k2 = 0; k2 < 4; k2++) {
            const uint32_t vk = vB + (uint32_t)(k2 * 16 * QK_PITCH);
            #pragma unroll
            for (int t = 0; t < 8; t++) {
                uint32_t vf[4];
                ldsm4t(vk + (uint32_t)(t << 5), vf);
                mma_f16(o[2 * t],     pf[k2], vf[0], vf[1]);
                mma_f16(o[2 * t + 1], pf[k2], vf[2], vf[3]);
            }
        }
    }

    // ---- epilogue: normalize, write g_O (fp16) ----
    {
        float inv0 = 1.0f / l0;
        float inv1 = 1.0f / l1;
        __half* op0 = g_O + (size_t)(b * L_ + q0 + wid * 16 + rr) * D_ + h * DK_;
        __half* op1 = op0 + 8 * D_;
        #pragma unroll
        for (int j = 0; j < 16; j++) {
            int n = j * 8 + (m_ << 1);
            *(uint32_t*)(op0 + n) = packh2(o[j][0] * inv0, o[j][1] * inv0);
            *(uint32_t*)(op1 + n) = packh2(o[j][2] * inv1, o[j][3] * inv1);
        }
    }
}

// ---------------- launch ----------------
extern "C" void kernel_launch(void* const* d_in, const int* in_sizes, int n_in,
                              void* d_out, int out_size) {
    const float* query = (const float*)d_in[0];
    const float* key_t = (const float*)d_in[1];
    const float* value = (const float*)d_in[2];
    // d_in[3] = mask (causal tril; unused)
    const float* Wq = (const float*)d_in[4];
    const float* Wk = (const float*)d_in[5];
    const float* Wv = (const float*)d_in[6];
    const float* Wo = (const float*)d_in[7];
    float* out = (float*)d_out;

    __half *Xq, *Xk, *Xv, *Whq, *Whk, *Whv, *Who, *Qb, *Kb, *Vb, *Ob;
    cudaGetSymbolAddress((void**)&Xq,  g_Xq);
    cudaGetSymbolAddress((void**)&Xk,  g_Xk);
    cudaGetSymbolAddress((void**)&Xv,  g_Xv);
    cudaGetSymbolAddress((void**)&Whq, g_Wq);
    cudaGetSymbolAddress((void**)&Whk, g_Wk);
    cudaGetSymbolAddress((void**)&Whv, g_Wv);
    cudaGetSymbolAddress((void**)&Who, g_Wo);
    cudaGetSymbolAddress((void**)&Qb,  g_Q);
    cudaGetSymbolAddress((void**)&Kb,  g_K);
    cudaGetSymbolAddress((void**)&Vb,  g_V);
    cudaGetSymbolAddress((void**)&Ob,  g_O);

    cudaFuncSetAttribute(gemm_f16_kernel, cudaFuncAttributeMaxDynamicSharedMemorySize,
                         GEMM_SMEM_BYTES);
    cudaFuncSetAttribute(gemm_f16_big_kernel, cudaFuncAttributeMaxDynamicSharedMemorySize,
                         GB_SMEM_BYTES);
    cudaFuncSetAttribute(attn_kernel, cudaFuncAttributeMaxDynamicSharedMemorySize,
                         ATTN_SMEM_BYTES);

    rope_table_kernel<<<512, 256>>>();

    const int n4_big = (M_ * D_) / 4;
    const int n4_w   = (D_ * D_) / 4;
    const int n4_kv  = (DKV_ * D_) / 4;
    f32_to_f16_kernel<<<n4_big / 256, 256>>>(query, Xq, n4_big);
    f32_to_f16_kernel<<<n4_big / 256, 256>>>(key_t, Xk, n4_big);
    f32_to_f16_kernel<<<n4_big / 256, 256>>>(value, Xv, n4_big);
    f32_to_f16_kernel<<<n4_w / 256, 256>>>(Wq, Whq, n4_w);
    f32_to_f16_kernel<<<n4_kv / 256, 256>>>(Wk, Whk, n4_kv);
    f32_to_f16_kernel<<<n4_kv / 256, 256>>>(Wv, Whv, n4_kv);
    f32_to_f16_kernel<<<n4_w / 256, 256>>>(Wo, Who, n4_w);

    // Projections
    gemm_f16_big_kernel<<<dim3(D_ / 256, M_ / 128), 256, GB_SMEM_BYTES>>>(
        Xq, Whq, Qb, M_, D_, D_, 1);
    gemm_f16_kernel<<<dim3(DKV_ / 128, M_ / 128), 256, GEMM_SMEM_BYTES>>>(
        Xk, Whk, Kb, M_, DKV_, D_, 1);
    gemm_f16_kernel<<<dim3(DKV_ / 128, M_ / 128), 256, GEMM_SMEM_BYTES>>>(
        Xv, Whv, Vb, M_, DKV_, D_, 1);

    // RoPE + clip
    rope_apply_kernel<<<(M_ * H_ * 64) / 256, 256>>>(Qb, H_, D_);
    rope_apply_kernel<<<(M_ * KVH_ * 64) / 256, 256>>>(Kb, KVH_, DKV_);

    // Attention (64q x 64kv tiles, FA2 register softmax)
    attn_kernel<<<dim3(L_ / 64, H_, B_), 128, ATTN_SMEM_BYTES>>>();

    // Output projection (fp32 out)
    gemm_f16_big_kernel<<<dim3(D_ / 256, M_ / 128), 256, GB_SMEM_BYTES>>>(
        Ob, Who, out, M_, D_, D_, 0);
}